// round 1
// baseline (speedup 1.0000x reference)
#include <cuda_runtime.h>

#define NN 2060
#define FF 901
#define MM 1778          // 901 + (2060-1183)
#define EE 131840        // NN*64
#define ET (EE + NN)     // edges + self loops
#define NTRAIN 100000
#define NTEST  30000
#define EPSF 1e-5f

// ---------------- scratch (static device globals; no allocation) ----------------
__device__ float    d_h[NN * FF];
__device__ float    d_g[NN * FF];
__device__ float    d_as[NN], d_ad[NN];
__device__ float    d_e[ET];
__device__ unsigned d_emax[NN];
__device__ float    d_denom[NN];
__device__ int      d_deg[NN];
__device__ int      d_rowptr[NN + 1];
__device__ int      d_wp[NN];
__device__ int      d_ssrc[ET];
__device__ float    d_salpha[ET];
__device__ double   d_st1[5];     // sums: dv, mi, dv^2, mi^2, dv*mi
__device__ double   d_st2[2];     // sums: u, u^2
__device__ float    d_gp[MM * 2];
__device__ float    d_xgbn[MM * 2];
__device__ float    d_consts[8]; // 0:mu1 1:rs1 2:muu 3:sc0 4:sc1
__device__ float    d_v3[512], d_v2[1024], d_v1[1802];
__device__ float    d_sA[MM], d_tB[MM];
__device__ float    d_bc;

__device__ __forceinline__ int drow(int m) { return m < 901 ? m : m + 282; }

__device__ __forceinline__ unsigned fenc(float f) {
    unsigned u = __float_as_uint(f);
    return (u & 0x80000000u) ? ~u : (u | 0x80000000u);
}
__device__ __forceinline__ float fdec(unsigned x) {
    return __uint_as_float((x & 0x80000000u) ? (x & 0x7FFFFFFFu) : ~x);
}

__device__ __forceinline__ float blockReduceSum(float v, float* sh) {
    int tid = threadIdx.x;
    sh[tid] = v; __syncthreads();
    for (int s = blockDim.x >> 1; s; s >>= 1) {
        if (tid < s) sh[tid] += sh[tid + s];
        __syncthreads();
    }
    float r = sh[0]; __syncthreads();
    return r;
}

// ---------------- init ----------------
__global__ void k_init() {
    int i = blockIdx.x * 256 + threadIdx.x;
    if (i < NN) { d_emax[i] = 0u; d_denom[i] = 0.f; d_deg[i] = 0; }
    if (i < 5) d_st1[i] = 0.0;
    if (i < 2) d_st2[i] = 0.0;
}

// ---------------- SGEMM: C[Ma,Nb] = A[Ma,Ka] @ B[Ka,Nb], fp32 ----------------
#define BM 128
#define BN 64
#define BK 16
__global__ __launch_bounds__(256) void k_sgemm(const float* __restrict__ A,
                                               const float* __restrict__ B,
                                               float* __restrict__ C,
                                               int Ma, int Ka, int Nb) {
    __shared__ float As[BK][BM + 4];
    __shared__ float Bs[BK][BN];
    int tid = threadIdx.x;
    int tx = tid & 15;   // N group (16 * 4 = 64)
    int ty = tid >> 4;   // M group (16 * 8 = 128)
    int brow = blockIdx.y * BM;
    int bcol = blockIdx.x * BN;
    float acc[8][4];
    #pragma unroll
    for (int i = 0; i < 8; i++)
        #pragma unroll
        for (int j = 0; j < 4; j++) acc[i][j] = 0.f;

    for (int k0 = 0; k0 < Ka; k0 += BK) {
        #pragma unroll
        for (int i = 0; i < 8; i++) {
            int idx = tid + i * 256;
            int r = idx >> 4, kk = idx & 15;
            int gr = brow + r, gk = k0 + kk;
            As[kk][r] = (gr < Ma && gk < Ka) ? A[(size_t)gr * Ka + gk] : 0.f;
        }
        #pragma unroll
        for (int i = 0; i < 4; i++) {
            int idx = tid + i * 256;
            int kk = idx >> 6, c = idx & 63;
            int gk = k0 + kk, gc = bcol + c;
            Bs[kk][c] = (gk < Ka && gc < Nb) ? B[(size_t)gk * Nb + gc] : 0.f;
        }
        __syncthreads();
        #pragma unroll
        for (int kk = 0; kk < BK; kk++) {
            float4 a0 = *(const float4*)&As[kk][ty * 8];
            float4 a1 = *(const float4*)&As[kk][ty * 8 + 4];
            float4 b0 = *(const float4*)&Bs[kk][tx * 4];
            float a[8] = {a0.x, a0.y, a0.z, a0.w, a1.x, a1.y, a1.z, a1.w};
            float b[4] = {b0.x, b0.y, b0.z, b0.w};
            #pragma unroll
            for (int i = 0; i < 8; i++)
                #pragma unroll
                for (int j = 0; j < 4; j++) acc[i][j] = fmaf(a[i], b[j], acc[i][j]);
        }
        __syncthreads();
    }
    #pragma unroll
    for (int i = 0; i < 8; i++) {
        int gr = brow + ty * 8 + i;
        if (gr >= Ma) continue;
        #pragma unroll
        for (int j = 0; j < 4; j++) {
            int gc = bcol + tx * 4 + j;
            if (gc < Nb) C[(size_t)gr * Nb + gc] = acc[i][j];
        }
    }
}

// ---------------- attention logits precompute ----------------
__global__ void k_asad(const float* __restrict__ h, const float* __restrict__ att_s,
                       const float* __restrict__ att_d) {
    int w = (blockIdx.x * blockDim.x + threadIdx.x) >> 5;
    int lane = threadIdx.x & 31;
    if (w >= NN) return;
    const float* hr = h + (size_t)w * FF;
    float s = 0.f, d = 0.f;
    for (int f = lane; f < FF; f += 32) { float hv = hr[f]; s += hv * att_s[f]; d += hv * att_d[f]; }
    for (int o = 16; o; o >>= 1) { s += __shfl_down_sync(~0u, s, o); d += __shfl_down_sync(~0u, d, o); }
    if (!lane) { d_as[w] = s; d_ad[w] = d; }
}

__global__ void k_edge1(const int* __restrict__ ei) {
    int j = blockIdx.x * 256 + threadIdx.x;
    if (j >= ET) return;
    int src, dst;
    if (j < EE) { src = ei[j]; dst = ei[EE + j]; } else { src = dst = j - EE; }
    float e = d_as[src] + d_ad[dst];
    e = e >= 0.f ? e : 0.2f * e;
    d_e[j] = e;
    atomicMax(&d_emax[dst], fenc(e));
    atomicAdd(&d_deg[dst], 1);
}

__global__ void k_edge2(const int* __restrict__ ei) {
    int j = blockIdx.x * 256 + threadIdx.x;
    if (j >= ET) return;
    int dst = (j < EE) ? ei[EE + j] : (j - EE);
    float ex = expf(d_e[j] - fdec(d_emax[dst]));
    d_e[j] = ex;
    atomicAdd(&d_denom[dst], ex);
}

__global__ void k_scan() {
    __shared__ int partial[256];
    int tid = threadIdx.x;
    const int CH = (NN + 255) / 256;   // 9
    int base = tid * CH;
    int loc[9];
    int sum = 0;
    for (int i = 0; i < CH; i++) {
        int idx = base + i;
        int v = (idx < NN) ? d_deg[idx] : 0;
        loc[i] = sum; sum += v;
    }
    partial[tid] = sum; __syncthreads();
    if (tid == 0) {
        int run = 0;
        for (int i = 0; i < 256; i++) { int v = partial[i]; partial[i] = run; run += v; }
        d_rowptr[NN] = run;
    }
    __syncthreads();
    int off = partial[tid];
    for (int i = 0; i < CH; i++) {
        int idx = base + i;
        if (idx < NN) { d_rowptr[idx] = off + loc[i]; d_wp[idx] = off + loc[i]; }
    }
}

__global__ void k_edge3(const int* __restrict__ ei) {
    int j = blockIdx.x * 256 + threadIdx.x;
    if (j >= ET) return;
    int src, dst;
    if (j < EE) { src = ei[j]; dst = ei[EE + j]; } else { src = dst = j - EE; }
    float alpha = d_e[j] / d_denom[dst];
    int pos = atomicAdd(&d_wp[dst], 1);
    d_ssrc[pos] = src;
    d_salpha[pos] = alpha;
}

// aggregate: g[d] = relu(sum_j alpha_j * h[src_j] + gat_b)
__global__ __launch_bounds__(256) void k_agg(const float* __restrict__ h,
                                             const float* __restrict__ gat_b) {
    int d = blockIdx.x;
    int start = d_rowptr[d], end = d_rowptr[d + 1];
    __shared__ int ss[128];
    __shared__ float sa[128];
    float acc[4] = {0.f, 0.f, 0.f, 0.f};
    for (int e0 = start; e0 < end; e0 += 128) {
        int cnt = min(128, end - e0);
        if (threadIdx.x < cnt) { ss[threadIdx.x] = d_ssrc[e0 + threadIdx.x]; sa[threadIdx.x] = d_salpha[e0 + threadIdx.x]; }
        __syncthreads();
        for (int i = 0; i < cnt; i++) {
            const float* hr = h + (size_t)ss[i] * FF;
            float al = sa[i];
            #pragma unroll
            for (int q = 0; q < 4; q++) {
                int f = threadIdx.x + q * 256;
                if (f < FF) acc[q] = fmaf(al, hr[f], acc[q]);
            }
        }
        __syncthreads();
    }
    #pragma unroll
    for (int q = 0; q < 4; q++) {
        int f = threadIdx.x + q * 256;
        if (f < FF) {
            float v = acc[q] + gat_b[f];
            d_g[(size_t)d * FF + f] = v > 0.f ? v : 0.f;
        }
    }
}

// ---------------- MLP collapse: v1 = W1 @ W2 @ W3 @ W4 ----------------
__global__ void k_matvec(const float* __restrict__ Wm, const float* __restrict__ v,
                         float* __restrict__ o, int rows, int cols) {
    int r = (blockIdx.x * blockDim.x + threadIdx.x) >> 5;
    int lane = threadIdx.x & 31;
    if (r >= rows) return;
    const float* Wr = Wm + (size_t)r * cols;
    float acc = 0.f;
    for (int c = lane; c < cols; c += 32) acc = fmaf(Wr[c], v[c], acc);
    for (int o2 = 16; o2; o2 >>= 1) acc += __shfl_down_sync(~0u, acc, o2);
    if (!lane) o[r] = acc;
}

__global__ void k_bc(const float* __restrict__ b1, const float* __restrict__ b2,
                     const float* __restrict__ b3, const float* __restrict__ b4,
                     const float* __restrict__ W4) {
    __shared__ float sh[256];
    float acc = 0.f;
    for (int i = threadIdx.x; i < 1024; i += 256) acc += b1[i] * d_v2[i];
    for (int i = threadIdx.x; i < 512; i += 256) acc += b2[i] * d_v3[i];
    for (int i = threadIdx.x; i < 64; i += 256) acc += b3[i] * W4[i];
    acc = blockReduceSum(acc, sh);
    if (threadIdx.x == 0) d_bc = acc + b4[0];
}

// ---------------- MS_CAM statistics ----------------
// per-row means (gp) + global sums for the local-path BN
__global__ __launch_bounds__(256) void k_rowstats(const float* __restrict__ mirna) {
    __shared__ float sh[256];
    int m = blockIdx.x;
    const float* dvr = d_g + (size_t)drow(m) * FF;
    const float* mir = mirna + (size_t)m * FF;
    float sdv = 0, smi = 0, sdv2 = 0, smi2 = 0, sx = 0;
    for (int f = threadIdx.x; f < FF; f += 256) {
        float dv = dvr[f], mi = mir[f];
        sdv += dv; smi += mi; sdv2 += dv * dv; smi2 += mi * mi; sx += dv * mi;
    }
    sdv = blockReduceSum(sdv, sh);
    smi = blockReduceSum(smi, sh);
    sdv2 = blockReduceSum(sdv2, sh);
    smi2 = blockReduceSum(smi2, sh);
    sx = blockReduceSum(sx, sh);
    if (threadIdx.x == 0) {
        d_gp[2 * m] = sdv / (float)FF;
        d_gp[2 * m + 1] = smi / (float)FF;
        atomicAdd(&d_st1[0], (double)sdv);
        atomicAdd(&d_st1[1], (double)smi);
        atomicAdd(&d_st1[2], (double)sdv2);
        atomicAdd(&d_st1[3], (double)smi2);
        atomicAdd(&d_st1[4], (double)sx);
    }
}

__global__ void k_fin1(const float* __restrict__ lw1, const float* __restrict__ lb1) {
    double cnt = (double)MM * FF;
    double a = lw1[0], b = lw1[1], c0 = lb1[0];
    double mean = (a * d_st1[0] + b * d_st1[1]) / cnt + c0;
    double ex2 = (a * a * d_st1[2] + b * b * d_st1[3] + 2.0 * a * b * d_st1[4]
                  + 2.0 * a * c0 * d_st1[0] + 2.0 * b * c0 * d_st1[1]) / cnt + c0 * c0;
    double var = ex2 - mean * mean;
    d_consts[0] = (float)mean;
    d_consts[1] = rsqrtf((float)var + EPSF);
}

__global__ __launch_bounds__(256) void k_stats2(const float* __restrict__ mirna,
                                                const float* __restrict__ lw1,
                                                const float* __restrict__ lb1) {
    __shared__ float sh[256];
    int m = blockIdx.x;
    const float* dvr = d_g + (size_t)drow(m) * FF;
    const float* mir = mirna + (size_t)m * FF;
    float a = lw1[0], b = lw1[1], c0 = lb1[0];
    float mu1 = d_consts[0], rs1 = d_consts[1];
    float su = 0, su2 = 0;
    for (int f = threadIdx.x; f < FF; f += 256) {
        float xlp = fmaf(a, dvr[f], fmaf(b, mir[f], c0));
        float u = (xlp - mu1) * rs1;
        u = u > 0.f ? u : 0.f;
        su += u; su2 += u * u;
    }
    su = blockReduceSum(su, sh);
    su2 = blockReduceSum(su2, sh);
    if (threadIdx.x == 0) {
        atomicAdd(&d_st2[0], (double)su);
        atomicAdd(&d_st2[1], (double)su2);
    }
}

__global__ void k_fin2(const float* __restrict__ lw2) {
    double cnt = (double)MM * FF;
    double muu = d_st2[0] / cnt;
    double varu = d_st2[1] / cnt - muu * muu;
    d_consts[2] = (float)muu;
    float w0 = lw2[0], w1 = lw2[1];
    d_consts[3] = w0 * rsqrtf((float)(w0 * w0 * varu) + EPSF);
    d_consts[4] = w1 * rsqrtf((float)(w1 * w1 * varu) + EPSF);
}

// global-path (xg) — whole thing in one block
__global__ __launch_bounds__(1024) void k_xg(const float* __restrict__ gw1, const float* __restrict__ gb1,
                                             const float* __restrict__ gw2, const float* __restrict__ gb2) {
    __shared__ float red[1024];
    int tid = threadIdx.x;
    float g10 = gw1[0], g11 = gw1[1], gb = gb1[0];
    bool h0 = tid < MM, h1 = tid + 1024 < MM;
    float x0 = 0.f, x1 = 0.f;
    if (h0) x0 = fmaf(d_gp[2 * tid], g10, fmaf(d_gp[2 * tid + 1], g11, gb));
    if (h1) x1 = fmaf(d_gp[2 * (tid + 1024)], g10, fmaf(d_gp[2 * (tid + 1024) + 1], g11, gb));

    red[tid] = (h0 ? x0 : 0.f) + (h1 ? x1 : 0.f); __syncthreads();
    for (int s = 512; s; s >>= 1) { if (tid < s) red[tid] += red[tid + s]; __syncthreads(); }
    float mean = red[0] / (float)MM; __syncthreads();

    float dx0 = x0 - mean, dx1 = x1 - mean;
    red[tid] = (h0 ? dx0 * dx0 : 0.f) + (h1 ? dx1 * dx1 : 0.f); __syncthreads();
    for (int s = 512; s; s >>= 1) { if (tid < s) red[tid] += red[tid + s]; __syncthreads(); }
    float rs = rsqrtf(red[0] / (float)MM + EPSF); __syncthreads();

    float u0 = h0 ? fmaxf(dx0 * rs, 0.f) : 0.f;
    float u1 = h1 ? fmaxf(dx1 * rs, 0.f) : 0.f;

    red[tid] = u0 + u1; __syncthreads();
    for (int s = 512; s; s >>= 1) { if (tid < s) red[tid] += red[tid + s]; __syncthreads(); }
    float mu = red[0] / (float)MM; __syncthreads();

    float du0 = u0 - mu, du1 = u1 - mu;
    red[tid] = (h0 ? du0 * du0 : 0.f) + (h1 ? du1 * du1 : 0.f); __syncthreads();
    for (int s = 512; s; s >>= 1) { if (tid < s) red[tid] += red[tid + s]; __syncthreads(); }
    float varg = red[0] / (float)MM;

    float w0 = gw2[0], w1 = gw2[1];
    float sc0 = w0 * rsqrtf(w0 * w0 * varg + EPSF);
    float sc1 = w1 * rsqrtf(w1 * w1 * varg + EPSF);
    if (h0) { d_xgbn[2 * tid] = du0 * sc0; d_xgbn[2 * tid + 1] = du0 * sc1; }
    if (h1) { d_xgbn[2 * (tid + 1024)] = du1 * sc0; d_xgbn[2 * (tid + 1024) + 1] = du1 * sc1; }
}

// fused MS_CAM + per-row collapsed-MLP dots: s[m], t[m]
__global__ __launch_bounds__(256) void k_fused(const float* __restrict__ mirna,
                                               const float* __restrict__ lw1,
                                               const float* __restrict__ lb1) {
    __shared__ float sh[256];
    int m = blockIdx.x;
    const float* dvr = d_g + (size_t)drow(m) * FF;
    const float* mir = mirna + (size_t)m * FF;
    float a = lw1[0], b = lw1[1], c0 = lb1[0];
    float mu1 = d_consts[0], rs1 = d_consts[1];
    float muu = d_consts[2], sc0 = d_consts[3], sc1 = d_consts[4];
    float xg0 = d_xgbn[2 * m], xg1 = d_xgbn[2 * m + 1];
    float accS = 0.f, accT = 0.f;
    for (int f = threadIdx.x; f < FF; f += 256) {
        float dv = dvr[f], mi = mir[f];
        float xlp = fmaf(a, dv, fmaf(b, mi, c0));
        float u = (xlp - mu1) * rs1;
        u = u > 0.f ? u : 0.f;
        float um = u - muu;
        float z0 = fmaf(um, sc0, xg0);
        float z1 = fmaf(um, sc1, xg1);
        float w0 = 1.f / (1.f + expf(-z0));
        float w1 = 1.f / (1.f + expf(-z1));
        float fu = 0.5f * (dv * w0 + mi * w1);
        accS = fmaf(fu, d_v1[f], accS);
        accT = fmaf(fu, d_v1[901 + f], accT);
    }
    accS = blockReduceSum(accS, sh);
    accT = blockReduceSum(accT, sh);
    if (threadIdx.x == 0) { d_sA[m] = accS; d_tB[m] = accT; }
}

__global__ void k_score(const int* __restrict__ tr, const int* __restrict__ te,
                        float* __restrict__ out) {
    int i = blockIdx.x * 256 + threadIdx.x;
    if (i >= NTRAIN + NTEST) return;
    int p0, p1;
    if (i < NTRAIN) { p0 = tr[2 * i]; p1 = tr[2 * i + 1]; }
    else { int j = i - NTRAIN; p0 = te[2 * j]; p1 = te[2 * j + 1]; }
    float z = d_sA[p0] + d_tB[p1] + d_bc;
    out[i] = 1.f / (1.f + expf(-z));
}

// ---------------- launch ----------------
extern "C" void kernel_launch(void* const* d_in, const int* in_sizes, int n_in,
                              void* d_out, int out_size) {
    const float* x_feat  = (const float*)d_in[0];
    const float* mirna   = (const float*)d_in[1];
    const float* Wg      = (const float*)d_in[2];
    const float* att_src = (const float*)d_in[3];
    const float* att_dst = (const float*)d_in[4];
    const float* gat_b   = (const float*)d_in[5];
    const float* lw1     = (const float*)d_in[6];
    const float* lb1     = (const float*)d_in[7];
    const float* lw2     = (const float*)d_in[8];
    const float* lb2     = (const float*)d_in[9];  (void)lb2; // cancels in BN
    const float* gw1     = (const float*)d_in[10];
    const float* gb1     = (const float*)d_in[11];
    const float* gw2     = (const float*)d_in[12];
    const float* gb2     = (const float*)d_in[13]; (void)gb2; // cancels in BN
    const float* W1      = (const float*)d_in[14];
    const float* b1      = (const float*)d_in[15];
    const float* W2      = (const float*)d_in[16];
    const float* b2      = (const float*)d_in[17];
    const float* W3      = (const float*)d_in[18];
    const float* b3      = (const float*)d_in[19];
    const float* W4      = (const float*)d_in[20];
    const float* b4      = (const float*)d_in[21];
    const int*   ei      = (const int*)d_in[22];
    const int*   trainS  = (const int*)d_in[23];
    const int*   testS   = (const int*)d_in[24];
    float* out = (float*)d_out;

    float* hptr;  cudaGetSymbolAddress((void**)&hptr, d_h);

    k_init<<<(NN + 255) / 256, 256>>>();

    // h = x_feat @ Wg
    dim3 gg((FF + BN - 1) / BN, (NN + BM - 1) / BM);
    k_sgemm<<<gg, 256>>>(x_feat, Wg, hptr, NN, NN, FF);

    k_asad<<<(NN + 7) / 8, 256>>>(hptr, att_src, att_dst);
    k_edge1<<<(ET + 255) / 256, 256>>>(ei);
    k_edge2<<<(ET + 255) / 256, 256>>>(ei);
    k_scan<<<1, 256>>>();
    k_edge3<<<(ET + 255) / 256, 256>>>(ei);
    k_agg<<<NN, 256>>>(hptr, gat_b);

    // collapse MLP: v3 = W3@W4, v2 = W2@v3, v1 = W1@v2
    float* v3p; cudaGetSymbolAddress((void**)&v3p, d_v3);
    float* v2p; cudaGetSymbolAddress((void**)&v2p, d_v2);
    float* v1p; cudaGetSymbolAddress((void**)&v1p, d_v1);
    k_matvec<<<(512 + 7) / 8, 256>>>(W3, W4, v3p, 512, 64);
    k_matvec<<<(1024 + 7) / 8, 256>>>(W2, v3p, v2p, 1024, 512);
    k_matvec<<<(1802 + 7) / 8, 256>>>(W1, v2p, v1p, 1802, 1024);
    k_bc<<<1, 256>>>(b1, b2, b3, b4, W4);

    // MS_CAM stats + fusion + per-row dots
    k_rowstats<<<MM, 256>>>(mirna);
    k_fin1<<<1, 1>>>(lw1, lb1);
    k_stats2<<<MM, 256>>>(mirna, lw1, lb1);
    k_fin2<<<1, 1>>>(lw2);
    k_xg<<<1, 1024>>>(gw1, gb1, gw2, gb2);
    k_fused<<<MM, 256>>>(mirna, lw1, lb1);

    k_score<<<(NTRAIN + NTEST + 255) / 256, 256>>>(trainS, testS, out);
}

// round 3
// speedup vs baseline: 1.4237x; 1.4237x over previous
#include <cuda_runtime.h>
#include <cuda_bf16.h>
#include <cstdint>
#include <stdint.h>

#define NN 2060
#define FF 901
#define MM 1778          // 901 + (2060-1183)
#define EE 131840        // NN*64
#define ET (EE + NN)     // edges + self loops
#define NTRAIN 100000
#define NTEST  30000
#define EPSF 1e-5f

// padded GEMM dims
#define MP 2176
#define KP 2080
#define NP 1024
#define GBM 128
#define GBN 128
#define GBK 16
#define SKA 24    // A smem row stride (bf16 elems)
#define SKB 136   // B smem row stride (bf16 elems)

// ---------------- scratch (static device globals; no allocation) ----------------
__device__ float    d_h[NN * FF];
__device__ float    d_g[NN * FF];
__device__ __nv_bfloat16 d_Ah[MP * KP], d_Al[MP * KP];
__device__ __nv_bfloat16 d_Bh[KP * NP], d_Bl[KP * NP];
__device__ float    d_as[NN], d_ad[NN];
__device__ float    d_e[ET];
__device__ unsigned d_emax[NN];
__device__ float    d_denom[NN];
__device__ int      d_deg[NN];
__device__ int      d_rowptr[NN + 1];
__device__ int      d_wp[NN];
__device__ int      d_ssrc[ET];
__device__ float    d_salpha[ET];
__device__ double   d_st1[5];
__device__ double   d_st2[2];
__device__ float    d_gp[MM * 2];
__device__ float    d_xgbn[MM * 2];
__device__ float    d_consts[8];
__device__ float    d_v3[512], d_v2[1024], d_v1[1802];
__device__ float    d_sA[MM], d_tB[MM];
__device__ float    d_bc;

__device__ __forceinline__ int drow(int m) { return m < 901 ? m : m + 282; }

__device__ __forceinline__ unsigned fenc(float f) {
    unsigned u = __float_as_uint(f);
    return (u & 0x80000000u) ? ~u : (u | 0x80000000u);
}
__device__ __forceinline__ float fdec(unsigned x) {
    return __uint_as_float((x & 0x80000000u) ? (x & 0x7FFFFFFFu) : ~x);
}

__device__ __forceinline__ float blockReduceSum(float v, float* sh) {
    int tid = threadIdx.x;
    sh[tid] = v; __syncthreads();
    for (int s = blockDim.x >> 1; s; s >>= 1) {
        if (tid < s) sh[tid] += sh[tid + s];
        __syncthreads();
    }
    float r = sh[0]; __syncthreads();
    return r;
}

// ---------------- init ----------------
__global__ void k_init() {
    int i = blockIdx.x * 256 + threadIdx.x;
    if (i < NN) { d_emax[i] = 0u; d_denom[i] = 0.f; d_deg[i] = 0; }
    if (i < 5) d_st1[i] = 0.0;
    if (i < 2) d_st2[i] = 0.0;
}

// ---------------- bf16 hi/lo conversion ----------------
__global__ __launch_bounds__(256) void k_convA(const float* __restrict__ x) {
    int idx = blockIdx.x * 256 + threadIdx.x;
    if (idx >= MP * KP) return;
    int m = idx / KP, k = idx - m * KP;
    float v = (m < NN && k < NN) ? x[(size_t)m * NN + k] : 0.f;
    __nv_bfloat16 hi = __float2bfloat16(v);
    float r = v - __bfloat162float(hi);
    d_Ah[idx] = hi;
    d_Al[idx] = __float2bfloat16(r);
}

__global__ __launch_bounds__(256) void k_convB(const float* __restrict__ w) {
    int idx = blockIdx.x * 256 + threadIdx.x;
    if (idx >= KP * NP) return;
    int k = idx / NP, n = idx - k * NP;
    float v = (k < NN && n < FF) ? w[(size_t)k * FF + n] : 0.f;
    __nv_bfloat16 hi = __float2bfloat16(v);
    float r = v - __bfloat162float(hi);
    d_Bh[idx] = hi;
    d_Bl[idx] = __float2bfloat16(r);
}

// ---------------- tensor-core split-bf16 GEMM ----------------
__device__ __forceinline__ void ldsm4(unsigned& r0, unsigned& r1, unsigned& r2, unsigned& r3, unsigned a) {
    asm volatile("ldmatrix.sync.aligned.m8n8.x4.shared.b16 {%0,%1,%2,%3}, [%4];"
                 : "=r"(r0), "=r"(r1), "=r"(r2), "=r"(r3) : "r"(a));
}
__device__ __forceinline__ void ldsm4t(unsigned& r0, unsigned& r1, unsigned& r2, unsigned& r3, unsigned a) {
    asm volatile("ldmatrix.sync.aligned.m8n8.x4.trans.shared.b16 {%0,%1,%2,%3}, [%4];"
                 : "=r"(r0), "=r"(r1), "=r"(r2), "=r"(r3) : "r"(a));
}
__device__ __forceinline__ void mma16816(float* c, const unsigned* a, unsigned b0, unsigned b1) {
    asm volatile("mma.sync.aligned.m16n8k16.row.col.f32.bf16.bf16.f32 "
                 "{%0,%1,%2,%3},{%4,%5,%6,%7},{%8,%9},{%0,%1,%2,%3};"
                 : "+f"(c[0]), "+f"(c[1]), "+f"(c[2]), "+f"(c[3])
                 : "r"(a[0]), "r"(a[1]), "r"(a[2]), "r"(a[3]), "r"(b0), "r"(b1));
}
__device__ __forceinline__ void cp16(unsigned s, const void* g) {
    asm volatile("cp.async.cg.shared.global [%0], [%1], 16;" :: "r"(s), "l"(g));
}

__global__ __launch_bounds__(256) void k_mma(float* __restrict__ C) {
    __shared__ __align__(16) __nv_bfloat16 sA[2][2][GBM * SKA];
    __shared__ __align__(16) __nv_bfloat16 sB[2][2][GBK * SKB];
    int tid = threadIdx.x;
    int warp = tid >> 5, lane = tid & 31;
    int wm = (warp & 3) * 32;
    int wn = (warp >> 2) * 64;
    int m0 = blockIdx.y * GBM;
    int n0 = blockIdx.x * GBN;

    float acc[2][8][4];
    #pragma unroll
    for (int i = 0; i < 2; i++)
        #pragma unroll
        for (int j = 0; j < 8; j++)
            #pragma unroll
            for (int q = 0; q < 4; q++) acc[i][j][q] = 0.f;

    // global load coordinates
    int ar = tid >> 1, ac = (tid & 1) * 8;   // A: 128 rows x 16 cols
    int br = tid >> 4, bc = (tid & 15) * 8;  // B: 16 rows x 128 cols
    const __nv_bfloat16* gAh = d_Ah + (size_t)(m0 + ar) * KP + ac;
    const __nv_bfloat16* gAl = d_Al + (size_t)(m0 + ar) * KP + ac;
    const __nv_bfloat16* gBh = d_Bh + (size_t)br * NP + n0 + bc;
    const __nv_bfloat16* gBl = d_Bl + (size_t)br * NP + n0 + bc;

    unsigned sAaddr[2][2], sBaddr[2][2];
    #pragma unroll
    for (int b = 0; b < 2; b++) {
        sAaddr[b][0] = (unsigned)__cvta_generic_to_shared(&sA[b][0][ar * SKA + ac]);
        sAaddr[b][1] = (unsigned)__cvta_generic_to_shared(&sA[b][1][ar * SKA + ac]);
        sBaddr[b][0] = (unsigned)__cvta_generic_to_shared(&sB[b][0][br * SKB + bc]);
        sBaddr[b][1] = (unsigned)__cvta_generic_to_shared(&sB[b][1][br * SKB + bc]);
    }

    const int NT = KP / GBK;  // 130

    // prologue: load tile 0
    cp16(sAaddr[0][0], gAh);
    cp16(sAaddr[0][1], gAl);
    cp16(sBaddr[0][0], gBh);
    cp16(sBaddr[0][1], gBl);
    asm volatile("cp.async.commit_group;");

    for (int t = 0; t < NT; t++) {
        int buf = t & 1;
        if (t + 1 < NT) {
            int nb = buf ^ 1;
            int k0 = (t + 1) * GBK;
            cp16(sAaddr[nb][0], gAh + k0);
            cp16(sAaddr[nb][1], gAl + k0);
            cp16(sBaddr[nb][0], gBh + (size_t)k0 * NP);
            cp16(sBaddr[nb][1], gBl + (size_t)k0 * NP);
            asm volatile("cp.async.commit_group;");
            asm volatile("cp.async.wait_group 1;");
        } else {
            asm volatile("cp.async.wait_group 0;");
        }
        __syncthreads();

        // fragment loads
        unsigned ah[2][4], al[2][4], bh[4][4], bl[4][4];
        #pragma unroll
        for (int mi = 0; mi < 2; mi++) {
            int row = wm + mi * 16 + (lane & 15);
            int colb = (lane >> 4) * 8;
            unsigned aoff = (unsigned)((row * SKA + colb) * 2);
            unsigned ad0 = (unsigned)__cvta_generic_to_shared(&sA[buf][0][0]) + aoff;
            unsigned ad1 = (unsigned)__cvta_generic_to_shared(&sA[buf][1][0]) + aoff;
            ldsm4(ah[mi][0], ah[mi][1], ah[mi][2], ah[mi][3], ad0);
            ldsm4(al[mi][0], al[mi][1], al[mi][2], al[mi][3], ad1);
        }
        #pragma unroll
        for (int nj = 0; nj < 4; nj++) {
            int row = lane & 15;
            int col = wn + nj * 16 + (lane >> 4) * 8;
            unsigned boff = (unsigned)((row * SKB + col) * 2);
            unsigned bd0 = (unsigned)__cvta_generic_to_shared(&sB[buf][0][0]) + boff;
            unsigned bd1 = (unsigned)__cvta_generic_to_shared(&sB[buf][1][0]) + boff;
            ldsm4t(bh[nj][0], bh[nj][1], bh[nj][2], bh[nj][3], bd0);
            ldsm4t(bl[nj][0], bl[nj][1], bl[nj][2], bl[nj][3], bd1);
        }

        #pragma unroll
        for (int mi = 0; mi < 2; mi++) {
            #pragma unroll
            for (int nj = 0; nj < 4; nj++) {
                #pragma unroll
                for (int hf = 0; hf < 2; hf++) {
                    float* c = acc[mi][nj * 2 + hf];
                    unsigned b0h = bh[nj][hf * 2], b1h = bh[nj][hf * 2 + 1];
                    unsigned b0l = bl[nj][hf * 2], b1l = bl[nj][hf * 2 + 1];
                    mma16816(c, ah[mi], b0h, b1h);   // Ah*Bh
                    mma16816(c, ah[mi], b0l, b1l);   // Ah*Bl
                    mma16816(c, al[mi], b0h, b1h);   // Al*Bh
                }
            }
        }
        __syncthreads();
    }

    // epilogue
    #pragma unroll
    for (int mi = 0; mi < 2; mi++) {
        #pragma unroll
        for (int t8 = 0; t8 < 8; t8++) {
            int m = m0 + wm + mi * 16 + (lane >> 2);
            int n = n0 + wn + t8 * 8 + (lane & 3) * 2;
            float* c = acc[mi][t8];
            if (m < NN) {
                if (n < FF)     C[(size_t)m * FF + n]     = c[0];
                if (n + 1 < FF) C[(size_t)m * FF + n + 1] = c[1];
            }
            if (m + 8 < NN) {
                if (n < FF)     C[(size_t)(m + 8) * FF + n]     = c[2];
                if (n + 1 < FF) C[(size_t)(m + 8) * FF + n + 1] = c[3];
            }
        }
    }
}

// ---------------- attention logits precompute ----------------
__global__ void k_asad(const float* __restrict__ h, const float* __restrict__ att_s,
                       const float* __restrict__ att_d) {
    int w = (blockIdx.x * blockDim.x + threadIdx.x) >> 5;
    int lane = threadIdx.x & 31;
    if (w >= NN) return;
    const float* hr = h + (size_t)w * FF;
    float s = 0.f, d = 0.f;
    for (int f = lane; f < FF; f += 32) { float hv = hr[f]; s += hv * att_s[f]; d += hv * att_d[f]; }
    for (int o = 16; o; o >>= 1) { s += __shfl_down_sync(~0u, s, o); d += __shfl_down_sync(~0u, d, o); }
    if (!lane) { d_as[w] = s; d_ad[w] = d; }
}

__global__ void k_edge1(const int* __restrict__ ei) {
    int j = blockIdx.x * 256 + threadIdx.x;
    if (j >= ET) return;
    int src, dst;
    if (j < EE) { src = ei[j]; dst = ei[EE + j]; } else { src = dst = j - EE; }
    float e = d_as[src] + d_ad[dst];
    e = e >= 0.f ? e : 0.2f * e;
    d_e[j] = e;
    atomicMax(&d_emax[dst], fenc(e));
    atomicAdd(&d_deg[dst], 1);
}

__global__ void k_edge2(const int* __restrict__ ei) {
    int j = blockIdx.x * 256 + threadIdx.x;
    if (j >= ET) return;
    int dst = (j < EE) ? ei[EE + j] : (j - EE);
    float ex = expf(d_e[j] - fdec(d_emax[dst]));
    d_e[j] = ex;
    atomicAdd(&d_denom[dst], ex);
}

__global__ void k_scan() {
    __shared__ int partial[256];
    int tid = threadIdx.x;
    const int CH = (NN + 255) / 256;   // 9
    int base = tid * CH;
    int loc[9];
    int sum = 0;
    for (int i = 0; i < CH; i++) {
        int idx = base + i;
        int v = (idx < NN) ? d_deg[idx] : 0;
        loc[i] = sum; sum += v;
    }
    partial[tid] = sum; __syncthreads();
    if (tid == 0) {
        int run = 0;
        for (int i = 0; i < 256; i++) { int v = partial[i]; partial[i] = run; run += v; }
        d_rowptr[NN] = run;
    }
    __syncthreads();
    int off = partial[tid];
    for (int i = 0; i < CH; i++) {
        int idx = base + i;
        if (idx < NN) { d_rowptr[idx] = off + loc[i]; d_wp[idx] = off + loc[i]; }
    }
}

__global__ void k_edge3(const int* __restrict__ ei) {
    int j = blockIdx.x * 256 + threadIdx.x;
    if (j >= ET) return;
    int src, dst;
    if (j < EE) { src = ei[j]; dst = ei[EE + j]; } else { src = dst = j - EE; }
    float alpha = d_e[j] / d_denom[dst];
    int pos = atomicAdd(&d_wp[dst], 1);
    d_ssrc[pos] = src;
    d_salpha[pos] = alpha;
}

// aggregate: g[d] = relu(sum_j alpha_j * h[src_j] + gat_b)
__global__ __launch_bounds__(256) void k_agg(const float* __restrict__ h,
                                             const float* __restrict__ gat_b) {
    int d = blockIdx.x;
    int start = d_rowptr[d], end = d_rowptr[d + 1];
    __shared__ int ss[128];
    __shared__ float sa[128];
    float acc[4] = {0.f, 0.f, 0.f, 0.f};
    for (int e0 = start; e0 < end; e0 += 128) {
        int cnt = min(128, end - e0);
        if (threadIdx.x < cnt) { ss[threadIdx.x] = d_ssrc[e0 + threadIdx.x]; sa[threadIdx.x] = d_salpha[e0 + threadIdx.x]; }
        __syncthreads();
        for (int i = 0; i < cnt; i++) {
            const float* hr = h + (size_t)ss[i] * FF;
            float al = sa[i];
            #pragma unroll
            for (int q = 0; q < 4; q++) {
                int f = threadIdx.x + q * 256;
                if (f < FF) acc[q] = fmaf(al, hr[f], acc[q]);
            }
        }
        __syncthreads();
    }
    #pragma unroll
    for (int q = 0; q < 4; q++) {
        int f = threadIdx.x + q * 256;
        if (f < FF) {
            float v = acc[q] + gat_b[f];
            d_g[(size_t)d * FF + f] = v > 0.f ? v : 0.f;
        }
    }
}

// ---------------- MLP collapse: v1 = W1 @ W2 @ W3 @ W4 ----------------
__global__ void k_matvec(const float* __restrict__ Wm, const float* __restrict__ v,
                         float* __restrict__ o, int rows, int cols) {
    int r = (blockIdx.x * blockDim.x + threadIdx.x) >> 5;
    int lane = threadIdx.x & 31;
    if (r >= rows) return;
    const float* Wr = Wm + (size_t)r * cols;
    float acc = 0.f;
    for (int c = lane; c < cols; c += 32) acc = fmaf(Wr[c], v[c], acc);
    for (int o2 = 16; o2; o2 >>= 1) acc += __shfl_down_sync(~0u, acc, o2);
    if (!lane) o[r] = acc;
}

__global__ void k_bc(const float* __restrict__ b1, const float* __restrict__ b2,
                     const float* __restrict__ b3, const float* __restrict__ b4,
                     const float* __restrict__ W4) {
    __shared__ float sh[256];
    float acc = 0.f;
    for (int i = threadIdx.x; i < 1024; i += 256) acc += b1[i] * d_v2[i];
    for (int i = threadIdx.x; i < 512; i += 256) acc += b2[i] * d_v3[i];
    for (int i = threadIdx.x; i < 64; i += 256) acc += b3[i] * W4[i];
    acc = blockReduceSum(acc, sh);
    if (threadIdx.x == 0) d_bc = acc + b4[0];
}

// ---------------- MS_CAM statistics ----------------
__global__ __launch_bounds__(256) void k_rowstats(const float* __restrict__ mirna) {
    __shared__ float sh[256];
    int m = blockIdx.x;
    const float* dvr = d_g + (size_t)drow(m) * FF;
    const float* mir = mirna + (size_t)m * FF;
    float sdv = 0, smi = 0, sdv2 = 0, smi2 = 0, sx = 0;
    for (int f = threadIdx.x; f < FF; f += 256) {
        float dv = dvr[f], mi = mir[f];
        sdv += dv; smi += mi; sdv2 += dv * dv; smi2 += mi * mi; sx += dv * mi;
    }
    sdv = blockReduceSum(sdv, sh);
    smi = blockReduceSum(smi, sh);
    sdv2 = blockReduceSum(sdv2, sh);
    smi2 = blockReduceSum(smi2, sh);
    sx = blockReduceSum(sx, sh);
    if (threadIdx.x == 0) {
        d_gp[2 * m] = sdv / (float)FF;
        d_gp[2 * m + 1] = smi / (float)FF;
        atomicAdd(&d_st1[0], (double)sdv);
        atomicAdd(&d_st1[1], (double)smi);
        atomicAdd(&d_st1[2], (double)sdv2);
        atomicAdd(&d_st1[3], (double)smi2);
        atomicAdd(&d_st1[4], (double)sx);
    }
}

__global__ void k_fin1(const float* __restrict__ lw1, const float* __restrict__ lb1) {
    double cnt = (double)MM * FF;
    double a = lw1[0], b = lw1[1], c0 = lb1[0];
    double mean = (a * d_st1[0] + b * d_st1[1]) / cnt + c0;
    double ex2 = (a * a * d_st1[2] + b * b * d_st1[3] + 2.0 * a * b * d_st1[4]
                  + 2.0 * a * c0 * d_st1[0] + 2.0 * b * c0 * d_st1[1]) / cnt + c0 * c0;
    double var = ex2 - mean * mean;
    d_consts[0] = (float)mean;
    d_consts[1] = rsqrtf((float)var + EPSF);
}

__global__ __launch_bounds__(256) void k_stats2(const float* __restrict__ mirna,
                                                const float* __restrict__ lw1,
                                                const float* __restrict__ lb1) {
    __shared__ float sh[256];
    int m = blockIdx.x;
    const float* dvr = d_g + (size_t)drow(m) * FF;
    const float* mir = mirna + (size_t)m * FF;
    float a = lw1[0], b = lw1[1], c0 = lb1[0];
    float mu1 = d_consts[0], rs1 = d_consts[1];
    float su = 0, su2 = 0;
    for (int f = threadIdx.x; f < FF; f += 256) {
        float xlp = fmaf(a, dvr[f], fmaf(b, mir[f], c0));
        float u = (xlp - mu1) * rs1;
        u = u > 0.f ? u : 0.f;
        su += u; su2 += u * u;
    }
    su = blockReduceSum(su, sh);
    su2 = blockReduceSum(su2, sh);
    if (threadIdx.x == 0) {
        atomicAdd(&d_st2[0], (double)su);
        atomicAdd(&d_st2[1], (double)su2);
    }
}

__global__ void k_fin2(const float* __restrict__ lw2) {
    double cnt = (double)MM * FF;
    double muu = d_st2[0] / cnt;
    double varu = d_st2[1] / cnt - muu * muu;
    d_consts[2] = (float)muu;
    float w0 = lw2[0], w1 = lw2[1];
    d_consts[3] = w0 * rsqrtf((float)(w0 * w0 * varu) + EPSF);
    d_consts[4] = w1 * rsqrtf((float)(w1 * w1 * varu) + EPSF);
}

__global__ __launch_bounds__(1024) void k_xg(const float* __restrict__ gw1, const float* __restrict__ gb1,
                                             const float* __restrict__ gw2, const float* __restrict__ gb2) {
    __shared__ float red[1024];
    int tid = threadIdx.x;
    float g10 = gw1[0], g11 = gw1[1], gb = gb1[0];
    bool h0 = tid < MM, h1 = tid + 1024 < MM;
    float x0 = 0.f, x1 = 0.f;
    if (h0) x0 = fmaf(d_gp[2 * tid], g10, fmaf(d_gp[2 * tid + 1], g11, gb));
    if (h1) x1 = fmaf(d_gp[2 * (tid + 1024)], g10, fmaf(d_gp[2 * (tid + 1024) + 1], g11, gb));

    red[tid] = (h0 ? x0 : 0.f) + (h1 ? x1 : 0.f); __syncthreads();
    for (int s = 512; s; s >>= 1) { if (tid < s) red[tid] += red[tid + s]; __syncthreads(); }
    float mean = red[0] / (float)MM; __syncthreads();

    float dx0 = x0 - mean, dx1 = x1 - mean;
    red[tid] = (h0 ? dx0 * dx0 : 0.f) + (h1 ? dx1 * dx1 : 0.f); __syncthreads();
    for (int s = 512; s; s >>= 1) { if (tid < s) red[tid] += red[tid + s]; __syncthreads(); }
    float rs = rsqrtf(red[0] / (float)MM + EPSF); __syncthreads();

    float u0 = h0 ? fmaxf(dx0 * rs, 0.f) : 0.f;
    float u1 = h1 ? fmaxf(dx1 * rs, 0.f) : 0.f;

    red[tid] = u0 + u1; __syncthreads();
    for (int s = 512; s; s >>= 1) { if (tid < s) red[tid] += red[tid + s]; __syncthreads(); }
    float mu = red[0] / (float)MM; __syncthreads();

    float du0 = u0 - mu, du1 = u1 - mu;
    red[tid] = (h0 ? du0 * du0 : 0.f) + (h1 ? du1 * du1 : 0.f); __syncthreads();
    for (int s = 512; s; s >>= 1) { if (tid < s) red[tid] += red[tid + s]; __syncthreads(); }
    float varg = red[0] / (float)MM;

    float w0 = gw2[0], w1 = gw2[1];
    float sc0 = w0 * rsqrtf(w0 * w0 * varg + EPSF);
    float sc1 = w1 * rsqrtf(w1 * w1 * varg + EPSF);
    if (h0) { d_xgbn[2 * tid] = du0 * sc0; d_xgbn[2 * tid + 1] = du0 * sc1; }
    if (h1) { d_xgbn[2 * (tid + 1024)] = du1 * sc0; d_xgbn[2 * (tid + 1024) + 1] = du1 * sc1; }
}

__global__ __launch_bounds__(256) void k_fused(const float* __restrict__ mirna,
                                               const float* __restrict__ lw1,
                                               const float* __restrict__ lb1) {
    __shared__ float sh[256];
    int m = blockIdx.x;
    const float* dvr = d_g + (size_t)drow(m) * FF;
    const float* mir = mirna + (size_t)m * FF;
    float a = lw1[0], b = lw1[1], c0 = lb1[0];
    float mu1 = d_consts[0], rs1 = d_consts[1];
    float muu = d_consts[2], sc0 = d_consts[3], sc1 = d_consts[4];
    float xg0 = d_xgbn[2 * m], xg1 = d_xgbn[2 * m + 1];
    float accS = 0.f, accT = 0.f;
    for (int f = threadIdx.x; f < FF; f += 256) {
        float dv = dvr[f], mi = mir[f];
        float xlp = fmaf(a, dv, fmaf(b, mi, c0));
        float u = (xlp - mu1) * rs1;
        u = u > 0.f ? u : 0.f;
        float um = u - muu;
        float z0 = fmaf(um, sc0, xg0);
        float z1 = fmaf(um, sc1, xg1);
        float w0 = 1.f / (1.f + expf(-z0));
        float w1 = 1.f / (1.f + expf(-z1));
        float fu = 0.5f * (dv * w0 + mi * w1);
        accS = fmaf(fu, d_v1[f], accS);
        accT = fmaf(fu, d_v1[901 + f], accT);
    }
    accS = blockReduceSum(accS, sh);
    accT = blockReduceSum(accT, sh);
    if (threadIdx.x == 0) { d_sA[m] = accS; d_tB[m] = accT; }
}

__global__ void k_score(const int* __restrict__ tr, const int* __restrict__ te,
                        float* __restrict__ out) {
    int i = blockIdx.x * 256 + threadIdx.x;
    if (i >= NTRAIN + NTEST) return;
    int p0, p1;
    if (i < NTRAIN) { p0 = tr[2 * i]; p1 = tr[2 * i + 1]; }
    else { int j = i - NTRAIN; p0 = te[2 * j]; p1 = te[2 * j + 1]; }
    float z = d_sA[p0] + d_tB[p1] + d_bc;
    out[i] = 1.f / (1.f + expf(-z));
}

// ---------------- launch ----------------
extern "C" void kernel_launch(void* const* d_in, const int* in_sizes, int n_in,
                              void* d_out, int out_size) {
    const float* x_feat  = (const float*)d_in[0];
    const float* mirna   = (const float*)d_in[1];
    const float* Wg      = (const float*)d_in[2];
    const float* att_src = (const float*)d_in[3];
    const float* att_dst = (const float*)d_in[4];
    const float* gat_b   = (const float*)d_in[5];
    const float* lw1     = (const float*)d_in[6];
    const float* lb1     = (const float*)d_in[7];
    const float* lw2     = (const float*)d_in[8];
    const float* gw1     = (const float*)d_in[10];
    const float* gb1     = (const float*)d_in[11];
    const float* gw2     = (const float*)d_in[12];
    const float* gb2     = (const float*)d_in[13];
    const float* W1      = (const float*)d_in[14];
    const float* b1      = (const float*)d_in[15];
    const float* W2      = (const float*)d_in[16];
    const float* b2      = (const float*)d_in[17];
    const float* W3      = (const float*)d_in[18];
    const float* b3      = (const float*)d_in[19];
    const float* W4      = (const float*)d_in[20];
    const float* b4      = (const float*)d_in[21];
    const int*   ei      = (const int*)d_in[22];
    const int*   trainS  = (const int*)d_in[23];
    const int*   testS   = (const int*)d_in[24];
    float* out = (float*)d_out;

    float* hptr;  cudaGetSymbolAddress((void**)&hptr, d_h);

    k_init<<<(NN + 255) / 256, 256>>>();

    // h = x_feat @ Wg via split-bf16 tensor cores
    k_convA<<<(MP * KP + 255) / 256, 256>>>(x_feat);
    k_convB<<<(KP * NP + 255) / 256, 256>>>(Wg);
    dim3 gg(NP / GBN, MP / GBM);   // 8 x 17 = 136 blocks
    k_mma<<<gg, 256>>>(hptr);

    k_asad<<<(NN + 7) / 8, 256>>>(hptr, att_src, att_dst);
    k_edge1<<<(ET + 255) / 256, 256>>>(ei);
    k_edge2<<<(ET + 255) / 256, 256>>>(ei);
    k_scan<<<1, 256>>>();
    k_edge3<<<(ET + 255) / 256, 256>>>(ei);
    k_agg<<<NN, 256>>>(hptr, gat_b);

    // collapse MLP: v3 = W3@W4, v2 = W2@v3, v1 = W1@v2
    float* v3p; cudaGetSymbolAddress((void**)&v3p, d_v3);
    float* v2p; cudaGetSymbolAddress((void**)&v2p, d_v2);
    float* v1p; cudaGetSymbolAddress((void**)&v1p, d_v1);
    k_matvec<<<(512 + 7) / 8, 256>>>(W3, W4, v3p, 512, 64);
    k_matvec<<<(1024 + 7) / 8, 256>>>(W2, v3p, v2p, 1024, 512);
    k_matvec<<<(1802 + 7) / 8, 256>>>(W1, v2p, v1p, 1802, 1024);
    k_bc<<<1, 256>>>(b1, b2, b3, b4, W4);

    // MS_CAM stats + fusion + per-row dots
    k_rowstats<<<MM, 256>>>(mirna);
    k_fin1<<<1, 1>>>(lw1, lb1);
    k_stats2<<<MM, 256>>>(mirna, lw1, lb1);
    k_fin2<<<1, 1>>>(lw2);
    k_xg<<<1, 1024>>>(gw1, gb1, gw2, gb2);
    k_fused<<<MM, 256>>>(mirna, lw1, lb1);

    k_score<<<(NTRAIN + NTEST + 255) / 256, 256>>>(trainS, testS, out);
}

// round 4
// speedup vs baseline: 1.5445x; 1.0849x over previous
#include <cuda_runtime.h>
#include <cuda_bf16.h>
#include <cstdint>
#include <stdint.h>

#define NN 2060
#define FF 901
#define MM 1778          // 901 + (2060-1183)
#define EE 131840        // NN*64
#define ET (EE + NN)     // edges + self loops
#define NTRAIN 100000
#define NTEST  30000
#define EPSF 1e-5f

// padded GEMM dims
#define MP 2176
#define KP 2080
#define NP 1024
#define GBM 128
#define GBN 128
#define GBK 32
#define SKA 40     // A smem row stride (bf16 elems)
#define SKB 136    // B smem row stride (bf16 elems)
#define ASZ_B (GBM * SKA * 2)          // 10240 bytes per A (hi or lo) stage
#define BSZ_B (GBK * SKB * 2)          // 8704 bytes per B (hi or lo) stage
#define STG_B (2 * ASZ_B + 2 * BSZ_B)  // 37888 bytes per stage
#define SMEM_TOT (3 * STG_B)           // 113664 bytes

// ---------------- scratch (static device globals; no allocation) ----------------
__device__ float    d_h[NN * FF];
__device__ float    d_g[NN * FF];
__device__ __nv_bfloat16 d_Ah[MP * KP], d_Al[MP * KP];
__device__ __nv_bfloat16 d_Bh[KP * NP], d_Bl[KP * NP];
__device__ float    d_as[NN], d_ad[NN];
__device__ float    d_e[ET];
__device__ unsigned d_emax[NN];
__device__ float    d_denom[NN];
__device__ int      d_deg[NN];
__device__ int      d_rowptr[NN + 1];
__device__ int      d_wp[NN];
__device__ int      d_ssrc[ET];
__device__ float    d_salpha[ET];
__device__ double   d_st1[5];
__device__ double   d_st2[2];
__device__ float    d_gp[MM * 2];
__device__ float    d_xgbn[MM * 2];
__device__ float    d_consts[8];
__device__ float    d_v3[512], d_v2[1024], d_v1[1802];
__device__ float    d_sA[MM], d_tB[MM];
__device__ float    d_bc;

__device__ __forceinline__ int drow(int m) { return m < 901 ? m : m + 282; }

__device__ __forceinline__ unsigned fenc(float f) {
    unsigned u = __float_as_uint(f);
    return (u & 0x80000000u) ? ~u : (u | 0x80000000u);
}
__device__ __forceinline__ float fdec(unsigned x) {
    return __uint_as_float((x & 0x80000000u) ? (x & 0x7FFFFFFFu) : ~x);
}

__device__ __forceinline__ float blockReduceSum(float v, float* sh) {
    int tid = threadIdx.x;
    sh[tid] = v; __syncthreads();
    for (int s = blockDim.x >> 1; s; s >>= 1) {
        if (tid < s) sh[tid] += sh[tid + s];
        __syncthreads();
    }
    float r = sh[0]; __syncthreads();
    return r;
}

// ---------------- init ----------------
__global__ void k_init() {
    int i = blockIdx.x * 256 + threadIdx.x;
    if (i < NN) { d_emax[i] = 0u; d_denom[i] = 0.f; d_deg[i] = 0; }
    if (i < 5) d_st1[i] = 0.0;
    if (i < 2) d_st2[i] = 0.0;
}

// ---------------- bf16 hi/lo conversion (vectorized) ----------------
__device__ __forceinline__ unsigned pack2(__nv_bfloat16 a, __nv_bfloat16 b) {
    return ((unsigned)__bfloat16_as_ushort(b) << 16) | (unsigned)__bfloat16_as_ushort(a);
}

__global__ __launch_bounds__(256) void k_convA(const float* __restrict__ x) {
    int i4 = (blockIdx.x * 256 + threadIdx.x) * 4;
    if (i4 >= MP * KP) return;
    int m = i4 / KP, k = i4 - m * KP;
    float v[4];
    if (m < NN && k + 4 <= NN) {   // NN%4==0, KP%4==0 -> no straddle
        float4 t = *(const float4*)(x + (size_t)m * NN + k);
        v[0] = t.x; v[1] = t.y; v[2] = t.z; v[3] = t.w;
    } else {
        v[0] = v[1] = v[2] = v[3] = 0.f;
    }
    __nv_bfloat16 h[4], l[4];
    #pragma unroll
    for (int j = 0; j < 4; j++) {
        h[j] = __float2bfloat16(v[j]);
        l[j] = __float2bfloat16(v[j] - __bfloat162float(h[j]));
    }
    *(uint2*)(d_Ah + i4) = make_uint2(pack2(h[0], h[1]), pack2(h[2], h[3]));
    *(uint2*)(d_Al + i4) = make_uint2(pack2(l[0], l[1]), pack2(l[2], l[3]));
}

__global__ __launch_bounds__(256) void k_convB(const float* __restrict__ w) {
    int i4 = (blockIdx.x * 256 + threadIdx.x) * 4;
    if (i4 >= KP * NP) return;
    int k = i4 / NP, n = i4 - k * NP;
    float v[4];
    #pragma unroll
    for (int j = 0; j < 4; j++) {
        int nn = n + j;
        v[j] = (k < NN && nn < FF) ? w[(size_t)k * FF + nn] : 0.f;
    }
    __nv_bfloat16 h[4], l[4];
    #pragma unroll
    for (int j = 0; j < 4; j++) {
        h[j] = __float2bfloat16(v[j]);
        l[j] = __float2bfloat16(v[j] - __bfloat162float(h[j]));
    }
    *(uint2*)(d_Bh + i4) = make_uint2(pack2(h[0], h[1]), pack2(h[2], h[3]));
    *(uint2*)(d_Bl + i4) = make_uint2(pack2(l[0], l[1]), pack2(l[2], l[3]));
}

// ---------------- tensor-core split-bf16 GEMM ----------------
__device__ __forceinline__ void ldsm4(unsigned& r0, unsigned& r1, unsigned& r2, unsigned& r3, unsigned a) {
    asm volatile("ldmatrix.sync.aligned.m8n8.x4.shared.b16 {%0,%1,%2,%3}, [%4];"
                 : "=r"(r0), "=r"(r1), "=r"(r2), "=r"(r3) : "r"(a));
}
__device__ __forceinline__ void ldsm4t(unsigned& r0, unsigned& r1, unsigned& r2, unsigned& r3, unsigned a) {
    asm volatile("ldmatrix.sync.aligned.m8n8.x4.trans.shared.b16 {%0,%1,%2,%3}, [%4];"
                 : "=r"(r0), "=r"(r1), "=r"(r2), "=r"(r3) : "r"(a));
}
__device__ __forceinline__ void mma16816(float* c, const unsigned* a, unsigned b0, unsigned b1) {
    asm volatile("mma.sync.aligned.m16n8k16.row.col.f32.bf16.bf16.f32 "
                 "{%0,%1,%2,%3},{%4,%5,%6,%7},{%8,%9},{%0,%1,%2,%3};"
                 : "+f"(c[0]), "+f"(c[1]), "+f"(c[2]), "+f"(c[3])
                 : "r"(a[0]), "r"(a[1]), "r"(a[2]), "r"(a[3]), "r"(b0), "r"(b1));
}
__device__ __forceinline__ void cp16(unsigned s, const void* g) {
    asm volatile("cp.async.cg.shared.global [%0], [%1], 16;" :: "r"(s), "l"(g));
}

__device__ __forceinline__ void load_stage(unsigned sbase, int stage, int k0,
                                           int tid, int m0, int n0) {
    unsigned st = sbase + stage * STG_B;
    #pragma unroll
    for (int it = 0; it < 2; it++) {
        int slot = tid + it * 256;
        // A: 128 rows x 32 cols bf16, 4 x 16B chunks per row
        int arow = slot >> 2, acg = (slot & 3) * 8;
        unsigned adst = st + (unsigned)(arow * SKA + acg) * 2;
        size_t agoff = (size_t)(m0 + arow) * KP + k0 + acg;
        cp16(adst, d_Ah + agoff);
        cp16(adst + ASZ_B, d_Al + agoff);
        // B: 32 rows x 128 cols bf16, 16 x 16B chunks per row
        int brow = slot >> 4, bcg = (slot & 15) * 8;
        unsigned bdst = st + 2 * ASZ_B + (unsigned)(brow * SKB + bcg) * 2;
        size_t bgoff = (size_t)(k0 + brow) * NP + n0 + bcg;
        cp16(bdst, d_Bh + bgoff);
        cp16(bdst + BSZ_B, d_Bl + bgoff);
    }
}

__global__ __launch_bounds__(256) void k_mma(float* __restrict__ C) {
    extern __shared__ __align__(16) __nv_bfloat16 smem[];
    unsigned sbase = (unsigned)__cvta_generic_to_shared(smem);
    int tid = threadIdx.x;
    int warp = tid >> 5, lane = tid & 31;
    int wm = (warp & 3) * 32;
    int wn = (warp >> 2) * 64;
    int m0 = blockIdx.y * GBM;
    int n0 = blockIdx.x * GBN;

    float acc[2][8][4];
    #pragma unroll
    for (int i = 0; i < 2; i++)
        #pragma unroll
        for (int j = 0; j < 8; j++)
            #pragma unroll
            for (int q = 0; q < 4; q++) acc[i][j][q] = 0.f;

    const int NT = KP / GBK;  // 65

    // prologue: stages 0 and 1
    load_stage(sbase, 0, 0, tid, m0, n0);
    asm volatile("cp.async.commit_group;");
    load_stage(sbase, 1, GBK, tid, m0, n0);
    asm volatile("cp.async.commit_group;");

    int buf = 0;
    for (int t = 0; t < NT; t++) {
        if (t + 2 < NT) {
            int nb = (t + 2) % 3;
            load_stage(sbase, nb, (t + 2) * GBK, tid, m0, n0);
            asm volatile("cp.async.commit_group;");
            asm volatile("cp.async.wait_group 2;");
        } else if (t + 1 < NT) {
            asm volatile("cp.async.wait_group 1;");
        } else {
            asm volatile("cp.async.wait_group 0;");
        }
        __syncthreads();

        unsigned abase = sbase + buf * STG_B;
        unsigned bbase = abase + 2 * ASZ_B;

        #pragma unroll
        for (int ks = 0; ks < 2; ks++) {
            unsigned ah[2][4], al[2][4], bh[4][4], bl[4][4];
            #pragma unroll
            for (int mi = 0; mi < 2; mi++) {
                int row = wm + mi * 16 + (lane & 15);
                int col = ks * 16 + (lane >> 4) * 8;
                unsigned off = (unsigned)(row * SKA + col) * 2;
                ldsm4(ah[mi][0], ah[mi][1], ah[mi][2], ah[mi][3], abase + off);
                ldsm4(al[mi][0], al[mi][1], al[mi][2], al[mi][3], abase + ASZ_B + off);
            }
            #pragma unroll
            for (int nj = 0; nj < 4; nj++) {
                int row = ks * 16 + (lane & 15);
                int col = wn + nj * 16 + (lane >> 4) * 8;
                unsigned off = (unsigned)(row * SKB + col) * 2;
                ldsm4t(bh[nj][0], bh[nj][1], bh[nj][2], bh[nj][3], bbase + off);
                ldsm4t(bl[nj][0], bl[nj][1], bl[nj][2], bl[nj][3], bbase + BSZ_B + off);
            }
            #pragma unroll
            for (int mi = 0; mi < 2; mi++) {
                #pragma unroll
                for (int nj = 0; nj < 4; nj++) {
                    #pragma unroll
                    for (int hf = 0; hf < 2; hf++) {
                        float* c = acc[mi][nj * 2 + hf];
                        unsigned b0h = bh[nj][hf * 2], b1h = bh[nj][hf * 2 + 1];
                        unsigned b0l = bl[nj][hf * 2], b1l = bl[nj][hf * 2 + 1];
                        mma16816(c, ah[mi], b0h, b1h);   // Ah*Bh
                        mma16816(c, ah[mi], b0l, b1l);   // Ah*Bl
                        mma16816(c, al[mi], b0h, b1h);   // Al*Bh
                    }
                }
            }
        }
        __syncthreads();
        buf = (buf + 1) % 3;
    }

    // epilogue
    #pragma unroll
    for (int mi = 0; mi < 2; mi++) {
        #pragma unroll
        for (int t8 = 0; t8 < 8; t8++) {
            int m = m0 + wm + mi * 16 + (lane >> 2);
            int n = n0 + wn + t8 * 8 + (lane & 3) * 2;
            float* c = acc[mi][t8];
            if (m < NN) {
                if (n < FF)     C[(size_t)m * FF + n]     = c[0];
                if (n + 1 < FF) C[(size_t)m * FF + n + 1] = c[1];
            }
            if (m + 8 < NN) {
                if (n < FF)     C[(size_t)(m + 8) * FF + n]     = c[2];
                if (n + 1 < FF) C[(size_t)(m + 8) * FF + n + 1] = c[3];
            }
        }
    }
}

// ---------------- attention logits precompute ----------------
__global__ void k_asad(const float* __restrict__ h, const float* __restrict__ att_s,
                       const float* __restrict__ att_d) {
    int w = (blockIdx.x * blockDim.x + threadIdx.x) >> 5;
    int lane = threadIdx.x & 31;
    if (w >= NN) return;
    const float* hr = h + (size_t)w * FF;
    float s = 0.f, d = 0.f;
    for (int f = lane; f < FF; f += 32) { float hv = hr[f]; s += hv * att_s[f]; d += hv * att_d[f]; }
    for (int o = 16; o; o >>= 1) { s += __shfl_down_sync(~0u, s, o); d += __shfl_down_sync(~0u, d, o); }
    if (!lane) { d_as[w] = s; d_ad[w] = d; }
}

__global__ void k_edge1(const int* __restrict__ ei) {
    int j = blockIdx.x * 256 + threadIdx.x;
    if (j >= ET) return;
    int src, dst;
    if (j < EE) { src = ei[j]; dst = ei[EE + j]; } else { src = dst = j - EE; }
    float e = d_as[src] + d_ad[dst];
    e = e >= 0.f ? e : 0.2f * e;
    d_e[j] = e;
    atomicMax(&d_emax[dst], fenc(e));
    atomicAdd(&d_deg[dst], 1);
}

__global__ void k_edge2(const int* __restrict__ ei) {
    int j = blockIdx.x * 256 + threadIdx.x;
    if (j >= ET) return;
    int dst = (j < EE) ? ei[EE + j] : (j - EE);
    float ex = expf(d_e[j] - fdec(d_emax[dst]));
    d_e[j] = ex;
    atomicAdd(&d_denom[dst], ex);
}

__global__ void k_scan() {
    __shared__ int partial[256];
    int tid = threadIdx.x;
    const int CH = (NN + 255) / 256;   // 9
    int base = tid * CH;
    int loc[9];
    int sum = 0;
    for (int i = 0; i < CH; i++) {
        int idx = base + i;
        int v = (idx < NN) ? d_deg[idx] : 0;
        loc[i] = sum; sum += v;
    }
    partial[tid] = sum; __syncthreads();
    if (tid == 0) {
        int run = 0;
        for (int i = 0; i < 256; i++) { int v = partial[i]; partial[i] = run; run += v; }
        d_rowptr[NN] = run;
    }
    __syncthreads();
    int off = partial[tid];
    for (int i = 0; i < CH; i++) {
        int idx = base + i;
        if (idx < NN) { d_rowptr[idx] = off + loc[i]; d_wp[idx] = off + loc[i]; }
    }
}

__global__ void k_edge3(const int* __restrict__ ei) {
    int j = blockIdx.x * 256 + threadIdx.x;
    if (j >= ET) return;
    int src, dst;
    if (j < EE) { src = ei[j]; dst = ei[EE + j]; } else { src = dst = j - EE; }
    float alpha = d_e[j] / d_denom[dst];
    int pos = atomicAdd(&d_wp[dst], 1);
    d_ssrc[pos] = src;
    d_salpha[pos] = alpha;
}

// aggregate: g[d] = relu(sum_j alpha_j * h[src_j] + gat_b)
__global__ __launch_bounds__(256) void k_agg(const float* __restrict__ h,
                                             const float* __restrict__ gat_b) {
    int d = blockIdx.x;
    int start = d_rowptr[d], end = d_rowptr[d + 1];
    __shared__ int ss[128];
    __shared__ float sa[128];
    float acc[4] = {0.f, 0.f, 0.f, 0.f};
    for (int e0 = start; e0 < end; e0 += 128) {
        int cnt = min(128, end - e0);
        if (threadIdx.x < cnt) { ss[threadIdx.x] = d_ssrc[e0 + threadIdx.x]; sa[threadIdx.x] = d_salpha[e0 + threadIdx.x]; }
        __syncthreads();
        for (int i = 0; i < cnt; i++) {
            const float* hr = h + (size_t)ss[i] * FF;
            float al = sa[i];
            #pragma unroll
            for (int q = 0; q < 4; q++) {
                int f = threadIdx.x + q * 256;
                if (f < FF) acc[q] = fmaf(al, hr[f], acc[q]);
            }
        }
        __syncthreads();
    }
    #pragma unroll
    for (int q = 0; q < 4; q++) {
        int f = threadIdx.x + q * 256;
        if (f < FF) {
            float v = acc[q] + gat_b[f];
            d_g[(size_t)d * FF + f] = v > 0.f ? v : 0.f;
        }
    }
}

// ---------------- MLP collapse: v1 = W1 @ W2 @ W3 @ W4 ----------------
__global__ void k_matvec(const float* __restrict__ Wm, const float* __restrict__ v,
                         float* __restrict__ o, int rows, int cols) {
    int r = (blockIdx.x * blockDim.x + threadIdx.x) >> 5;
    int lane = threadIdx.x & 31;
    if (r >= rows) return;
    const float* Wr = Wm + (size_t)r * cols;
    float acc = 0.f;
    for (int c = lane; c < cols; c += 32) acc = fmaf(Wr[c], v[c], acc);
    for (int o2 = 16; o2; o2 >>= 1) acc += __shfl_down_sync(~0u, acc, o2);
    if (!lane) o[r] = acc;
}

__global__ void k_bc(const float* __restrict__ b1, const float* __restrict__ b2,
                     const float* __restrict__ b3, const float* __restrict__ b4,
                     const float* __restrict__ W4) {
    __shared__ float sh[256];
    float acc = 0.f;
    for (int i = threadIdx.x; i < 1024; i += 256) acc += b1[i] * d_v2[i];
    for (int i = threadIdx.x; i < 512; i += 256) acc += b2[i] * d_v3[i];
    for (int i = threadIdx.x; i < 64; i += 256) acc += b3[i] * W4[i];
    acc = blockReduceSum(acc, sh);
    if (threadIdx.x == 0) d_bc = acc + b4[0];
}

// ---------------- MS_CAM statistics ----------------
__global__ __launch_bounds__(256) void k_rowstats(const float* __restrict__ mirna) {
    __shared__ float sh[256];
    int m = blockIdx.x;
    const float* dvr = d_g + (size_t)drow(m) * FF;
    const float* mir = mirna + (size_t)m * FF;
    float sdv = 0, smi = 0, sdv2 = 0, smi2 = 0, sx = 0;
    for (int f = threadIdx.x; f < FF; f += 256) {
        float dv = dvr[f], mi = mir[f];
        sdv += dv; smi += mi; sdv2 += dv * dv; smi2 += mi * mi; sx += dv * mi;
    }
    sdv = blockReduceSum(sdv, sh);
    smi = blockReduceSum(smi, sh);
    sdv2 = blockReduceSum(sdv2, sh);
    smi2 = blockReduceSum(smi2, sh);
    sx = blockReduceSum(sx, sh);
    if (threadIdx.x == 0) {
        d_gp[2 * m] = sdv / (float)FF;
        d_gp[2 * m + 1] = smi / (float)FF;
        atomicAdd(&d_st1[0], (double)sdv);
        atomicAdd(&d_st1[1], (double)smi);
        atomicAdd(&d_st1[2], (double)sdv2);
        atomicAdd(&d_st1[3], (double)smi2);
        atomicAdd(&d_st1[4], (double)sx);
    }
}

__global__ void k_fin1(const float* __restrict__ lw1, const float* __restrict__ lb1) {
    double cnt = (double)MM * FF;
    double a = lw1[0], b = lw1[1], c0 = lb1[0];
    double mean = (a * d_st1[0] + b * d_st1[1]) / cnt + c0;
    double ex2 = (a * a * d_st1[2] + b * b * d_st1[3] + 2.0 * a * b * d_st1[4]
                  + 2.0 * a * c0 * d_st1[0] + 2.0 * b * c0 * d_st1[1]) / cnt + c0 * c0;
    double var = ex2 - mean * mean;
    d_consts[0] = (float)mean;
    d_consts[1] = rsqrtf((float)var + EPSF);
}

__global__ __launch_bounds__(256) void k_stats2(const float* __restrict__ mirna,
                                                const float* __restrict__ lw1,
                                                const float* __restrict__ lb1) {
    __shared__ float sh[256];
    int m = blockIdx.x;
    const float* dvr = d_g + (size_t)drow(m) * FF;
    const float* mir = mirna + (size_t)m * FF;
    float a = lw1[0], b = lw1[1], c0 = lb1[0];
    float mu1 = d_consts[0], rs1 = d_consts[1];
    float su = 0, su2 = 0;
    for (int f = threadIdx.x; f < FF; f += 256) {
        float xlp = fmaf(a, dvr[f], fmaf(b, mir[f], c0));
        float u = (xlp - mu1) * rs1;
        u = u > 0.f ? u : 0.f;
        su += u; su2 += u * u;
    }
    su = blockReduceSum(su, sh);
    su2 = blockReduceSum(su2, sh);
    if (threadIdx.x == 0) {
        atomicAdd(&d_st2[0], (double)su);
        atomicAdd(&d_st2[1], (double)su2);
    }
}

__global__ void k_fin2(const float* __restrict__ lw2) {
    double cnt = (double)MM * FF;
    double muu = d_st2[0] / cnt;
    double varu = d_st2[1] / cnt - muu * muu;
    d_consts[2] = (float)muu;
    float w0 = lw2[0], w1 = lw2[1];
    d_consts[3] = w0 * rsqrtf((float)(w0 * w0 * varu) + EPSF);
    d_consts[4] = w1 * rsqrtf((float)(w1 * w1 * varu) + EPSF);
}

__global__ __launch_bounds__(1024) void k_xg(const float* __restrict__ gw1, const float* __restrict__ gb1,
                                             const float* __restrict__ gw2, const float* __restrict__ gb2) {
    __shared__ float red[1024];
    int tid = threadIdx.x;
    float g10 = gw1[0], g11 = gw1[1], gb = gb1[0];
    bool h0 = tid < MM, h1 = tid + 1024 < MM;
    float x0 = 0.f, x1 = 0.f;
    if (h0) x0 = fmaf(d_gp[2 * tid], g10, fmaf(d_gp[2 * tid + 1], g11, gb));
    if (h1) x1 = fmaf(d_gp[2 * (tid + 1024)], g10, fmaf(d_gp[2 * (tid + 1024) + 1], g11, gb));

    red[tid] = (h0 ? x0 : 0.f) + (h1 ? x1 : 0.f); __syncthreads();
    for (int s = 512; s; s >>= 1) { if (tid < s) red[tid] += red[tid + s]; __syncthreads(); }
    float mean = red[0] / (float)MM; __syncthreads();

    float dx0 = x0 - mean, dx1 = x1 - mean;
    red[tid] = (h0 ? dx0 * dx0 : 0.f) + (h1 ? dx1 * dx1 : 0.f); __syncthreads();
    for (int s = 512; s; s >>= 1) { if (tid < s) red[tid] += red[tid + s]; __syncthreads(); }
    float rs = rsqrtf(red[0] / (float)MM + EPSF); __syncthreads();

    float u0 = h0 ? fmaxf(dx0 * rs, 0.f) : 0.f;
    float u1 = h1 ? fmaxf(dx1 * rs, 0.f) : 0.f;

    red[tid] = u0 + u1; __syncthreads();
    for (int s = 512; s; s >>= 1) { if (tid < s) red[tid] += red[tid + s]; __syncthreads(); }
    float mu = red[0] / (float)MM; __syncthreads();

    float du0 = u0 - mu, du1 = u1 - mu;
    red[tid] = (h0 ? du0 * du0 : 0.f) + (h1 ? du1 * du1 : 0.f); __syncthreads();
    for (int s = 512; s; s >>= 1) { if (tid < s) red[tid] += red[tid + s]; __syncthreads(); }
    float varg = red[0] / (float)MM;

    float w0 = gw2[0], w1 = gw2[1];
    float sc0 = w0 * rsqrtf(w0 * w0 * varg + EPSF);
    float sc1 = w1 * rsqrtf(w1 * w1 * varg + EPSF);
    if (h0) { d_xgbn[2 * tid] = du0 * sc0; d_xgbn[2 * tid + 1] = du0 * sc1; }
    if (h1) { d_xgbn[2 * (tid + 1024)] = du1 * sc0; d_xgbn[2 * (tid + 1024) + 1] = du1 * sc1; }
}

__global__ __launch_bounds__(256) void k_fused(const float* __restrict__ mirna,
                                               const float* __restrict__ lw1,
                                               const float* __restrict__ lb1) {
    __shared__ float sh[256];
    int m = blockIdx.x;
    const float* dvr = d_g + (size_t)drow(m) * FF;
    const float* mir = mirna + (size_t)m * FF;
    float a = lw1[0], b = lw1[1], c0 = lb1[0];
    float mu1 = d_consts[0], rs1 = d_consts[1];
    float muu = d_consts[2], sc0 = d_consts[3], sc1 = d_consts[4];
    float xg0 = d_xgbn[2 * m], xg1 = d_xgbn[2 * m + 1];
    float accS = 0.f, accT = 0.f;
    for (int f = threadIdx.x; f < FF; f += 256) {
        float dv = dvr[f], mi = mir[f];
        float xlp = fmaf(a, dv, fmaf(b, mi, c0));
        float u = (xlp - mu1) * rs1;
        u = u > 0.f ? u : 0.f;
        float um = u - muu;
        float z0 = fmaf(um, sc0, xg0);
        float z1 = fmaf(um, sc1, xg1);
        float w0 = 1.f / (1.f + expf(-z0));
        float w1 = 1.f / (1.f + expf(-z1));
        float fu = 0.5f * (dv * w0 + mi * w1);
        accS = fmaf(fu, d_v1[f], accS);
        accT = fmaf(fu, d_v1[901 + f], accT);
    }
    accS = blockReduceSum(accS, sh);
    accT = blockReduceSum(accT, sh);
    if (threadIdx.x == 0) { d_sA[m] = accS; d_tB[m] = accT; }
}

__global__ void k_score(const int* __restrict__ tr, const int* __restrict__ te,
                        float* __restrict__ out) {
    int i = blockIdx.x * 256 + threadIdx.x;
    if (i >= NTRAIN + NTEST) return;
    int p0, p1;
    if (i < NTRAIN) { p0 = tr[2 * i]; p1 = tr[2 * i + 1]; }
    else { int j = i - NTRAIN; p0 = te[2 * j]; p1 = te[2 * j + 1]; }
    float z = d_sA[p0] + d_tB[p1] + d_bc;
    out[i] = 1.f / (1.f + expf(-z));
}

// ---------------- launch ----------------
extern "C" void kernel_launch(void* const* d_in, const int* in_sizes, int n_in,
                              void* d_out, int out_size) {
    const float* x_feat  = (const float*)d_in[0];
    const float* mirna   = (const float*)d_in[1];
    const float* Wg      = (const float*)d_in[2];
    const float* att_src = (const float*)d_in[3];
    const float* att_dst = (const float*)d_in[4];
    const float* gat_b   = (const float*)d_in[5];
    const float* lw1     = (const float*)d_in[6];
    const float* lb1     = (const float*)d_in[7];
    const float* lw2     = (const float*)d_in[8];
    const float* gw1     = (const float*)d_in[10];
    const float* gb1     = (const float*)d_in[11];
    const float* gw2     = (const float*)d_in[12];
    const float* gb2     = (const float*)d_in[13];
    const float* W1      = (const float*)d_in[14];
    const float* b1      = (const float*)d_in[15];
    const float* W2      = (const float*)d_in[16];
    const float* b2      = (const float*)d_in[17];
    const float* W3      = (const float*)d_in[18];
    const float* b3      = (const float*)d_in[19];
    const float* W4      = (const float*)d_in[20];
    const float* b4      = (const float*)d_in[21];
    const int*   ei      = (const int*)d_in[22];
    const int*   trainS  = (const int*)d_in[23];
    const int*   testS   = (const int*)d_in[24];
    float* out = (float*)d_out;

    float* hptr;  cudaGetSymbolAddress((void**)&hptr, d_h);

    cudaFuncSetAttribute(k_mma, cudaFuncAttributeMaxDynamicSharedMemorySize, SMEM_TOT);

    k_init<<<(NN + 255) / 256, 256>>>();

    // h = x_feat @ Wg via split-bf16 tensor cores
    k_convA<<<(MP * KP / 4 + 255) / 256, 256>>>(x_feat);
    k_convB<<<(KP * NP / 4 + 255) / 256, 256>>>(Wg);
    dim3 gg(NP / GBN, MP / GBM);   // 8 x 17 = 136 blocks
    k_mma<<<gg, 256, SMEM_TOT>>>(hptr);

    k_asad<<<(NN + 7) / 8, 256>>>(hptr, att_src, att_dst);
    k_edge1<<<(ET + 255) / 256, 256>>>(ei);
    k_edge2<<<(ET + 255) / 256, 256>>>(ei);
    k_scan<<<1, 256>>>();
    k_edge3<<<(ET + 255) / 256, 256>>>(ei);
    k_agg<<<NN, 256>>>(hptr, gat_b);

    // collapse MLP: v3 = W3@W4, v2 = W2@v3, v1 = W1@v2
    float* v3p; cudaGetSymbolAddress((void**)&v3p, d_v3);
    float* v2p; cudaGetSymbolAddress((void**)&v2p, d_v2);
    float* v1p; cudaGetSymbolAddress((void**)&v1p, d_v1);
    k_matvec<<<(512 + 7) / 8, 256>>>(W3, W4, v3p, 512, 64);
    k_matvec<<<(1024 + 7) / 8, 256>>>(W2, v3p, v2p, 1024, 512);
    k_matvec<<<(1802 + 7) / 8, 256>>>(W1, v2p, v1p, 1802, 1024);
    k_bc<<<1, 256>>>(b1, b2, b3, b4, W4);

    // MS_CAM stats + fusion + per-row dots
    k_rowstats<<<MM, 256>>>(mirna);
    k_fin1<<<1, 1>>>(lw1, lb1);
    k_stats2<<<MM, 256>>>(mirna, lw1, lb1);
    k_fin2<<<1, 1>>>(lw2);
    k_xg<<<1, 1024>>>(gw1, gb1, gw2, gb2);
    k_fused<<<MM, 256>>>(mirna, lw1, lb1);

    k_score<<<(NTRAIN + NTEST + 255) / 256, 256>>>(trainS, testS, out);
}

// round 8
// speedup vs baseline: 1.8406x; 1.1917x over previous
#include <cuda_runtime.h>
#include <cuda_fp16.h>
#include <cstdint>
#include <stdint.h>

#define NN 2060
#define FF 901
#define MM 1778          // 901 + (2060-1183)
#define EE 131840        // NN*64
#define ET (EE + NN)     // edges + self loops
#define NTRAIN 100000
#define NTEST  30000
#define EPSF 1e-5f

// padded GEMM dims
#define MP 2176          // 17 * 128
#define KP2 2112         // 33 * 64
#define NP 1024          // 8 * 128
#define GBK 64
#define SKA 72           // A smem row stride (fp16 elems), 64 + 8 pad
#define SKB 136          // B smem row stride (fp16 elems), 128 + 8 pad
#define A_BYTES (128 * SKA * 2)            // 18432
#define B_BYTES (GBK * SKB * 2)            // 17408
#define STG (2 * A_BYTES + B_BYTES)        // 54272
#define SMEM_TOT (2 * STG)                 // 108544

// ---------------- scratch (static device globals; no allocation) ----------------
__device__ float    d_h[NN * FF];
__device__ float    d_g[NN * FF];
__device__ __half   d_Ah[MP * KP2], d_Al[MP * KP2];
__device__ __half   d_Bh[KP2 * NP];        // [K, N] row-major, hi only
__device__ float    d_as[NN], d_ad[NN];
__device__ float    d_e[ET];
__device__ unsigned d_emax[NN];
__device__ float    d_denom[NN];
__device__ int      d_deg[NN];
__device__ int      d_rowptr[NN + 1];
__device__ int      d_wp[NN];
__device__ int      d_ssrc[ET];
__device__ float    d_salpha[ET];
__device__ double   d_st1[5];
__device__ double   d_st2[2];
__device__ float    d_gp[MM * 2];
__device__ float    d_xgbn[MM * 2];
__device__ float    d_consts[8];
__device__ float    d_v3[512], d_v2[1024], d_v1[1802];
__device__ float    d_sA[MM], d_tB[MM];
__device__ float    d_bc;

__device__ __forceinline__ int drow(int m) { return m < 901 ? m : m + 282; }

__device__ __forceinline__ unsigned fenc(float f) {
    unsigned u = __float_as_uint(f);
    return (u & 0x80000000u) ? ~u : (u | 0x80000000u);
}
__device__ __forceinline__ float fdec(unsigned x) {
    return __uint_as_float((x & 0x80000000u) ? (x & 0x7FFFFFFFu) : ~x);
}

__device__ __forceinline__ float blockReduceSum(float v, float* sh) {
    int tid = threadIdx.x;
    sh[tid] = v; __syncthreads();
    for (int s = blockDim.x >> 1; s; s >>= 1) {
        if (tid < s) sh[tid] += sh[tid + s];
        __syncthreads();
    }
    float r = sh[0]; __syncthreads();
    return r;
}

// ---------------- init ----------------
__global__ void k_init() {
    int i = blockIdx.x * 256 + threadIdx.x;
    if (i < NN) { d_emax[i] = 0u; d_denom[i] = 0.f; d_deg[i] = 0; }
    if (i < 5) d_st1[i] = 0.0;
    if (i < 2) d_st2[i] = 0.0;
}

// ---------------- fp16 hi/lo conversion ----------------
__device__ __forceinline__ unsigned pack2h(__half a, __half b) {
    return ((unsigned)__half_as_ushort(b) << 16) | (unsigned)__half_as_ushort(a);
}

__global__ __launch_bounds__(256) void k_convA(const float* __restrict__ x) {
    int i4 = (blockIdx.x * 256 + threadIdx.x) * 4;
    if (i4 >= MP * KP2) return;
    int m = i4 / KP2, k = i4 - m * KP2;
    float v[4];
    if (m < NN && k + 4 <= NN) {   // NN%4==0, KP2%4==0 -> no straddle
        float4 t = *(const float4*)(x + (size_t)m * NN + k);
        v[0] = t.x; v[1] = t.y; v[2] = t.z; v[3] = t.w;
    } else {
        v[0] = v[1] = v[2] = v[3] = 0.f;
    }
    __half h[4], l[4];
    #pragma unroll
    for (int j = 0; j < 4; j++) {
        h[j] = __float2half(v[j]);
        l[j] = __float2half(v[j] - __half2float(h[j]));
    }
    *(uint2*)(d_Ah + i4) = make_uint2(pack2h(h[0], h[1]), pack2h(h[2], h[3]));
    *(uint2*)(d_Al + i4) = make_uint2(pack2h(l[0], l[1]), pack2h(l[2], l[3]));
}

__global__ __launch_bounds__(256) void k_convB(const float* __restrict__ w) {
    int i4 = (blockIdx.x * 256 + threadIdx.x) * 4;
    if (i4 >= KP2 * NP) return;
    int k = i4 / NP, n = i4 - k * NP;
    __half h[4];
    #pragma unroll
    for (int j = 0; j < 4; j++) {
        int nn = n + j;
        float v = (k < NN && nn < FF) ? w[(size_t)k * FF + nn] : 0.f;
        h[j] = __float2half(v);
    }
    *(uint2*)(d_Bh + i4) = make_uint2(pack2h(h[0], h[1]), pack2h(h[2], h[3]));
}

// ---------------- tensor-core split-fp16 GEMM ----------------
__device__ __forceinline__ void ldsm4(unsigned& r0, unsigned& r1, unsigned& r2, unsigned& r3, unsigned a) {
    asm volatile("ldmatrix.sync.aligned.m8n8.x4.shared.b16 {%0,%1,%2,%3}, [%4];"
                 : "=r"(r0), "=r"(r1), "=r"(r2), "=r"(r3) : "r"(a));
}
__device__ __forceinline__ void ldsm4t(unsigned& r0, unsigned& r1, unsigned& r2, unsigned& r3, unsigned a) {
    asm volatile("ldmatrix.sync.aligned.m8n8.x4.trans.shared.b16 {%0,%1,%2,%3}, [%4];"
                 : "=r"(r0), "=r"(r1), "=r"(r2), "=r"(r3) : "r"(a));
}
__device__ __forceinline__ void mma16816(float* c, const unsigned* a, unsigned b0, unsigned b1) {
    asm volatile("mma.sync.aligned.m16n8k16.row.col.f32.f16.f16.f32 "
                 "{%0,%1,%2,%3},{%4,%5,%6,%7},{%8,%9},{%0,%1,%2,%3};"
                 : "+f"(c[0]), "+f"(c[1]), "+f"(c[2]), "+f"(c[3])
                 : "r"(a[0]), "r"(a[1]), "r"(a[2]), "r"(a[3]), "r"(b0), "r"(b1));
}
__device__ __forceinline__ void cp16(unsigned s, const void* g) {
    asm volatile("cp.async.cg.shared.global [%0], [%1], 16;" :: "r"(s), "l"(g));
}

__device__ __forceinline__ void load_stage(unsigned sbase, int stage, int k0,
                                           int tid, int m0, int n0) {
    unsigned st = sbase + stage * STG;
    #pragma unroll
    for (int i = 0; i < 4; i++) {
        int id = tid + i * 256;
        // A: 128 rows x 64 fp16, 8 x 16B chunks per row -> 1024 chunks
        int ar = id >> 3, ac = (id & 7) * 8;
        unsigned aoff = (unsigned)(ar * SKA + ac) * 2;
        size_t ag = (size_t)(m0 + ar) * KP2 + k0 + ac;
        cp16(st + aoff, d_Ah + ag);
        cp16(st + A_BYTES + aoff, d_Al + ag);
        // B: 64 rows x 128 fp16, 16 x 16B chunks per row -> 1024 chunks
        int br = id >> 4, bcg = (id & 15) * 8;
        unsigned boff = (unsigned)(br * SKB + bcg) * 2;
        cp16(st + 2 * A_BYTES + boff, d_Bh + (size_t)(k0 + br) * NP + n0 + bcg);
    }
}

__global__ __launch_bounds__(256) void k_mma(float* __restrict__ C) {
    extern __shared__ __align__(16) __half smem[];
    unsigned sbase = (unsigned)__cvta_generic_to_shared(smem);
    int tid = threadIdx.x;
    int warp = tid >> 5, lane = tid & 31;
    int wm = (warp & 3) * 32;
    int wn = (warp >> 2) * 64;
    int m0 = blockIdx.y * 128;
    int n0 = blockIdx.x * 128;

    float acc[2][8][4];
    #pragma unroll
    for (int i = 0; i < 2; i++)
        #pragma unroll
        for (int j = 0; j < 8; j++)
            #pragma unroll
            for (int q = 0; q < 4; q++) acc[i][j][q] = 0.f;

    const int NT = KP2 / GBK;  // 33

    load_stage(sbase, 0, 0, tid, m0, n0);
    asm volatile("cp.async.commit_group;");

    for (int t = 0; t < NT; t++) {
        if (t + 1 < NT) {
            load_stage(sbase, (t + 1) & 1, (t + 1) * GBK, tid, m0, n0);
            asm volatile("cp.async.commit_group;");
            asm volatile("cp.async.wait_group 1;");
        } else {
            asm volatile("cp.async.wait_group 0;");
        }
        __syncthreads();

        unsigned abase = sbase + (t & 1) * STG;
        unsigned bbase = abase + 2 * A_BYTES;

        #pragma unroll
        for (int ks = 0; ks < 4; ks++) {
            unsigned ah[2][4], al[2][4], bh[4][4];
            #pragma unroll
            for (int mi = 0; mi < 2; mi++) {
                int row = wm + mi * 16 + (lane & 15);
                int col = ks * 16 + (lane >> 4) * 8;
                unsigned off = (unsigned)(row * SKA + col) * 2;
                ldsm4(ah[mi][0], ah[mi][1], ah[mi][2], ah[mi][3], abase + off);
                ldsm4(al[mi][0], al[mi][1], al[mi][2], al[mi][3], abase + A_BYTES + off);
            }
            #pragma unroll
            for (int nj = 0; nj < 4; nj++) {
                int row = ks * 16 + (lane & 15);
                int col = wn + nj * 16 + (lane >> 4) * 8;
                unsigned off = (unsigned)(row * SKB + col) * 2;
                ldsm4t(bh[nj][0], bh[nj][1], bh[nj][2], bh[nj][3], bbase + off);
            }
            #pragma unroll
            for (int mi = 0; mi < 2; mi++) {
                #pragma unroll
                for (int nj = 0; nj < 4; nj++) {
                    #pragma unroll
                    for (int hf = 0; hf < 2; hf++) {
                        float* c = acc[mi][nj * 2 + hf];
                        unsigned b0 = bh[nj][hf * 2], b1 = bh[nj][hf * 2 + 1];
                        mma16816(c, ah[mi], b0, b1);   // Ah*Bh
                        mma16816(c, al[mi], b0, b1);   // Al*Bh
                    }
                }
            }
        }
        __syncthreads();
    }

    // epilogue
    #pragma unroll
    for (int mi = 0; mi < 2; mi++) {
        #pragma unroll
        for (int t8 = 0; t8 < 8; t8++) {
            int m = m0 + wm + mi * 16 + (lane >> 2);
            int n = n0 + wn + t8 * 8 + (lane & 3) * 2;
            float* c = acc[mi][t8];
            if (m < NN) {
                if (n < FF)     C[(size_t)m * FF + n]     = c[0];
                if (n + 1 < FF) C[(size_t)m * FF + n + 1] = c[1];
            }
            if (m + 8 < NN) {
                if (n < FF)     C[(size_t)(m + 8) * FF + n]     = c[2];
                if (n + 1 < FF) C[(size_t)(m + 8) * FF + n + 1] = c[3];
            }
        }
    }
}

// ---------------- attention logits precompute ----------------
__global__ void k_asad(const float* __restrict__ h, const float* __restrict__ att_s,
                       const float* __restrict__ att_d) {
    int w = (blockIdx.x * blockDim.x + threadIdx.x) >> 5;
    int lane = threadIdx.x & 31;
    if (w >= NN) return;
    const float* hr = h + (size_t)w * FF;
    float s = 0.f, d = 0.f;
    for (int f = lane; f < FF; f += 32) { float hv = hr[f]; s += hv * att_s[f]; d += hv * att_d[f]; }
    for (int o = 16; o; o >>= 1) { s += __shfl_down_sync(~0u, s, o); d += __shfl_down_sync(~0u, d, o); }
    if (!lane) { d_as[w] = s; d_ad[w] = d; }
}

__global__ void k_edge1(const int* __restrict__ ei) {
    int j = blockIdx.x * 256 + threadIdx.x;
    if (j >= ET) return;
    int src, dst;
    if (j < EE) { src = ei[j]; dst = ei[EE + j]; } else { src = dst = j - EE; }
    float e = d_as[src] + d_ad[dst];
    e = e >= 0.f ? e : 0.2f * e;
    d_e[j] = e;
    atomicMax(&d_emax[dst], fenc(e));
    atomicAdd(&d_deg[dst], 1);
}

__global__ void k_edge2(const int* __restrict__ ei) {
    int j = blockIdx.x * 256 + threadIdx.x;
    if (j >= ET) return;
    int dst = (j < EE) ? ei[EE + j] : (j - EE);
    float ex = expf(d_e[j] - fdec(d_emax[dst]));
    d_e[j] = ex;
    atomicAdd(&d_denom[dst], ex);
}

__global__ void k_scan() {
    __shared__ int partial[256];
    int tid = threadIdx.x;
    const int CH = (NN + 255) / 256;   // 9
    int base = tid * CH;
    int loc[9];
    int sum = 0;
    for (int i = 0; i < CH; i++) {
        int idx = base + i;
        int v = (idx < NN) ? d_deg[idx] : 0;
        loc[i] = sum; sum += v;
    }
    partial[tid] = sum; __syncthreads();
    if (tid == 0) {
        int run = 0;
        for (int i = 0; i < 256; i++) { int v = partial[i]; partial[i] = run; run += v; }
        d_rowptr[NN] = run;
    }
    __syncthreads();
    int off = partial[tid];
    for (int i = 0; i < CH; i++) {
        int idx = base + i;
        if (idx < NN) { d_rowptr[idx] = off + loc[i]; d_wp[idx] = off + loc[i]; }
    }
}

__global__ void k_edge3(const int* __restrict__ ei) {
    int j = blockIdx.x * 256 + threadIdx.x;
    if (j >= ET) return;
    int src, dst;
    if (j < EE) { src = ei[j]; dst = ei[EE + j]; } else { src = dst = j - EE; }
    float alpha = d_e[j] / d_denom[dst];
    int pos = atomicAdd(&d_wp[dst], 1);
    d_ssrc[pos] = src;
    d_salpha[pos] = alpha;
}

// aggregate only the 1778 rows consumed downstream
__global__ __launch_bounds__(256) void k_agg(const float* __restrict__ h,
                                             const float* __restrict__ gat_b) {
    int d = drow(blockIdx.x);
    int start = d_rowptr[d], end = d_rowptr[d + 1];
    __shared__ int ss[128];
    __shared__ float sa[128];
    float acc[4] = {0.f, 0.f, 0.f, 0.f};
    for (int e0 = start; e0 < end; e0 += 128) {
        int cnt = min(128, end - e0);
        if (threadIdx.x < cnt) { ss[threadIdx.x] = d_ssrc[e0 + threadIdx.x]; sa[threadIdx.x] = d_salpha[e0 + threadIdx.x]; }
        __syncthreads();
        for (int i = 0; i < cnt; i++) {
            const float* hr = h + (size_t)ss[i] * FF;
            float al = sa[i];
            #pragma unroll
            for (int q = 0; q < 4; q++) {
                int f = threadIdx.x + q * 256;
                if (f < FF) acc[q] = fmaf(al, hr[f], acc[q]);
            }
        }
        __syncthreads();
    }
    #pragma unroll
    for (int q = 0; q < 4; q++) {
        int f = threadIdx.x + q * 256;
        if (f < FF) {
            float v = acc[q] + gat_b[f];
            d_g[(size_t)d * FF + f] = v > 0.f ? v : 0.f;
        }
    }
}

// ---------------- MLP collapse: v1 = W1 @ W2 @ W3 @ W4 ----------------
__global__ void k_matvec(const float* __restrict__ Wm, const float* __restrict__ v,
                         float* __restrict__ o, int rows, int cols) {
    int r = (blockIdx.x * blockDim.x + threadIdx.x) >> 5;
    int lane = threadIdx.x & 31;
    if (r >= rows) return;
    const float* Wr = Wm + (size_t)r * cols;
    float acc = 0.f;
    for (int c = lane; c < cols; c += 32) acc = fmaf(Wr[c], v[c], acc);
    for (int o2 = 16; o2; o2 >>= 1) acc += __shfl_down_sync(~0u, acc, o2);
    if (!lane) o[r] = acc;
}

__global__ void k_bc(const float* __restrict__ b1, const float* __restrict__ b2,
                     const float* __restrict__ b3, const float* __restrict__ b4,
                     const float* __restrict__ W4) {
    __shared__ float sh[256];
    float acc = 0.f;
    for (int i = threadIdx.x; i < 1024; i += 256) acc += b1[i] * d_v2[i];
    for (int i = threadIdx.x; i < 512; i += 256) acc += b2[i] * d_v3[i];
    for (int i = threadIdx.x; i < 64; i += 256) acc += b3[i] * W4[i];
    acc = blockReduceSum(acc, sh);
    if (threadIdx.x == 0) d_bc = acc + b4[0];
}

// ---------------- MS_CAM statistics ----------------
__global__ __launch_bounds__(256) void k_rowstats(const float* __restrict__ mirna) {
    __shared__ float sh[256];
    int m = blockIdx.x;
    const float* dvr = d_g + (size_t)drow(m) * FF;
    const float* mir = mirna + (size_t)m * FF;
    float sdv = 0, smi = 0, sdv2 = 0, smi2 = 0, sx = 0;
    for (int f = threadIdx.x; f < FF; f += 256) {
        float dv = dvr[f], mi = mir[f];
        sdv += dv; smi += mi; sdv2 += dv * dv; smi2 += mi * mi; sx += dv * mi;
    }
    sdv = blockReduceSum(sdv, sh);
    smi = blockReduceSum(smi, sh);
    sdv2 = blockReduceSum(sdv2, sh);
    smi2 = blockReduceSum(smi2, sh);
    sx = blockReduceSum(sx, sh);
    if (threadIdx.x == 0) {
        d_gp[2 * m] = sdv / (float)FF;
        d_gp[2 * m + 1] = smi / (float)FF;
        atomicAdd(&d_st1[0], (double)sdv);
        atomicAdd(&d_st1[1], (double)smi);
        atomicAdd(&d_st1[2], (double)sdv2);
        atomicAdd(&d_st1[3], (double)smi2);
        atomicAdd(&d_st1[4], (double)sx);
    }
}

__global__ void k_fin1(const float* __restrict__ lw1, const float* __restrict__ lb1) {
    double cnt = (double)MM * FF;
    double a = lw1[0], b = lw1[1], c0 = lb1[0];
    double mean = (a * d_st1[0] + b * d_st1[1]) / cnt + c0;
    double ex2 = (a * a * d_st1[2] + b * b * d_st1[3] + 2.0 * a * b * d_st1[4]
                  + 2.0 * a * c0 * d_st1[0] + 2.0 * b * c0 * d_st1[1]) / cnt + c0 * c0;
    double var = ex2 - mean * mean;
    d_consts[0] = (float)mean;
    d_consts[1] = rsqrtf((float)var + EPSF);
}

__global__ __launch_bounds__(256) void k_stats2(const float* __restrict__ mirna,
                                                const float* __restrict__ lw1,
                                                const float* __restrict__ lb1) {
    __shared__ float sh[256];
    int m = blockIdx.x;
    const float* dvr = d_g + (size_t)drow(m) * FF;
    const float* mir = mirna + (size_t)m * FF;
    float a = lw1[0], b = lw1[1], c0 = lb1[0];
    float mu1 = d_consts[0], rs1 = d_consts[1];
    float su = 0, su2 = 0;
    for (int f = threadIdx.x; f < FF; f += 256) {
        float xlp = fmaf(a, dvr[f], fmaf(b, mir[f], c0));
        float u = (xlp - mu1) * rs1;
        u = u > 0.f ? u : 0.f;
        su += u; su2 += u * u;
    }
    su = blockReduceSum(su, sh);
    su2 = blockReduceSum(su2, sh);
    if (threadIdx.x == 0) {
        atomicAdd(&d_st2[0], (double)su);
        atomicAdd(&d_st2[1], (double)su2);
    }
}

__global__ void k_fin2(const float* __restrict__ lw2) {
    double cnt = (double)MM * FF;
    double muu = d_st2[0] / cnt;
    double varu = d_st2[1] / cnt - muu * muu;
    d_consts[2] = (float)muu;
    float w0 = lw2[0], w1 = lw2[1];
    d_consts[3] = w0 * rsqrtf((float)(w0 * w0 * varu) + EPSF);
    d_consts[4] = w1 * rsqrtf((float)(w1 * w1 * varu) + EPSF);
}

__global__ __launch_bounds__(1024) void k_xg(const float* __restrict__ gw1, const float* __restrict__ gb1,
                                             const float* __restrict__ gw2, const float* __restrict__ gb2) {
    __shared__ float red[1024];
    int tid = threadIdx.x;
    float g10 = gw1[0], g11 = gw1[1], gb = gb1[0];
    bool h0 = tid < MM, h1 = tid + 1024 < MM;
    float x0 = 0.f, x1 = 0.f;
    if (h0) x0 = fmaf(d_gp[2 * tid], g10, fmaf(d_gp[2 * tid + 1], g11, gb));
    if (h1) x1 = fmaf(d_gp[2 * (tid + 1024)], g10, fmaf(d_gp[2 * (tid + 1024) + 1], g11, gb));

    red[tid] = (h0 ? x0 : 0.f) + (h1 ? x1 : 0.f); __syncthreads();
    for (int s = 512; s; s >>= 1) { if (tid < s) red[tid] += red[tid + s]; __syncthreads(); }
    float mean = red[0] / (float)MM; __syncthreads();

    float dx0 = x0 - mean, dx1 = x1 - mean;
    red[tid] = (h0 ? dx0 * dx0 : 0.f) + (h1 ? dx1 * dx1 : 0.f); __syncthreads();
    for (int s = 512; s; s >>= 1) { if (tid < s) red[tid] += red[tid + s]; __syncthreads(); }
    float rs = rsqrtf(red[0] / (float)MM + EPSF); __syncthreads();

    float u0 = h0 ? fmaxf(dx0 * rs, 0.f) : 0.f;
    float u1 = h1 ? fmaxf(dx1 * rs, 0.f) : 0.f;

    red[tid] = u0 + u1; __syncthreads();
    for (int s = 512; s; s >>= 1) { if (tid < s) red[tid] += red[tid + s]; __syncthreads(); }
    float mu = red[0] / (float)MM; __syncthreads();

    float du0 = u0 - mu, du1 = u1 - mu;
    red[tid] = (h0 ? du0 * du0 : 0.f) + (h1 ? du1 * du1 : 0.f); __syncthreads();
    for (int s = 512; s; s >>= 1) { if (tid < s) red[tid] += red[tid + s]; __syncthreads(); }
    float varg = red[0] / (float)MM;

    float w0 = gw2[0], w1 = gw2[1];
    float sc0 = w0 * rsqrtf(w0 * w0 * varg + EPSF);
    float sc1 = w1 * rsqrtf(w1 * w1 * varg + EPSF);
    if (h0) { d_xgbn[2 * tid] = du0 * sc0; d_xgbn[2 * tid + 1] = du0 * sc1; }
    if (h1) { d_xgbn[2 * (tid + 1024)] = du1 * sc0; d_xgbn[2 * (tid + 1024) + 1] = du1 * sc1; }
}

__global__ __launch_bounds__(256) void k_fused(const float* __restrict__ mirna,
                                               const float* __restrict__ lw1,
                                               const float* __restrict__ lb1) {
    __shared__ float sh[256];
    int m = blockIdx.x;
    const float* dvr = d_g + (size_t)drow(m) * FF;
    const float* mir = mirna + (size_t)m * FF;
    float a = lw1[0], b = lw1[1], c0 = lb1[0];
    float mu1 = d_consts[0], rs1 = d_consts[1];
    float muu = d_consts[2], sc0 = d_consts[3], sc1 = d_consts[4];
    float xg0 = d_xgbn[2 * m], xg1 = d_xgbn[2 * m + 1];
    float accS = 0.f, accT = 0.f;
    for (int f = threadIdx.x; f < FF; f += 256) {
        float dv = dvr[f], mi = mir[f];
        float xlp = fmaf(a, dv, fmaf(b, mi, c0));
        float u = (xlp - mu1) * rs1;
        u = u > 0.f ? u : 0.f;
        float um = u - muu;
        float z0 = fmaf(um, sc0, xg0);
        float z1 = fmaf(um, sc1, xg1);
        float w0 = 1.f / (1.f + expf(-z0));
        float w1 = 1.f / (1.f + expf(-z1));
        float fu = 0.5f * (dv * w0 + mi * w1);
        accS = fmaf(fu, d_v1[f], accS);
        accT = fmaf(fu, d_v1[901 + f], accT);
    }
    accS = blockReduceSum(accS, sh);
    accT = blockReduceSum(accT, sh);
    if (threadIdx.x == 0) { d_sA[m] = accS; d_tB[m] = accT; }
}

__global__ void k_score(const int* __restrict__ tr, const int* __restrict__ te,
                        float* __restrict__ out) {
    int i = blockIdx.x * 256 + threadIdx.x;
    if (i >= NTRAIN + NTEST) return;
    int p0, p1;
    if (i < NTRAIN) { p0 = tr[2 * i]; p1 = tr[2 * i + 1]; }
    else { int j = i - NTRAIN; p0 = te[2 * j]; p1 = te[2 * j + 1]; }
    float z = d_sA[p0] + d_tB[p1] + d_bc;
    out[i] = 1.f / (1.f + expf(-z));
}

// ---------------- launch ----------------
extern "C" void kernel_launch(void* const* d_in, const int* in_sizes, int n_in,
                              void* d_out, int out_size) {
    const float* x_feat  = (const float*)d_in[0];
    const float* mirna   = (const float*)d_in[1];
    const float* Wg      = (const float*)d_in[2];
    const float* att_src = (const float*)d_in[3];
    const float* att_dst = (const float*)d_in[4];
    const float* gat_b   = (const float*)d_in[5];
    const float* lw1     = (const float*)d_in[6];
    const float* lb1     = (const float*)d_in[7];
    const float* lw2     = (const float*)d_in[8];
    const float* gw1     = (const float*)d_in[10];
    const float* gb1     = (const float*)d_in[11];
    const float* gw2     = (const float*)d_in[12];
    const float* gb2     = (const float*)d_in[13];
    const float* W1      = (const float*)d_in[14];
    const float* b1      = (const float*)d_in[15];
    const float* W2      = (const float*)d_in[16];
    const float* b2      = (const float*)d_in[17];
    const float* W3      = (const float*)d_in[18];
    const float* b3      = (const float*)d_in[19];
    const float* W4      = (const float*)d_in[20];
    const float* b4      = (const float*)d_in[21];
    const int*   ei      = (const int*)d_in[22];
    const int*   trainS  = (const int*)d_in[23];
    const int*   testS   = (const int*)d_in[24];
    float* out = (float*)d_out;

    float* hptr;  cudaGetSymbolAddress((void**)&hptr, d_h);

    cudaFuncSetAttribute(k_mma, cudaFuncAttributeMaxDynamicSharedMemorySize, SMEM_TOT);

    k_init<<<(NN + 255) / 256, 256>>>();

    // h = x_feat @ Wg via split-fp16 tensor cores (2-product)
    k_convA<<<(MP * KP2 / 4 + 255) / 256, 256>>>(x_feat);
    k_convB<<<(KP2 * NP / 4 + 255) / 256, 256>>>(Wg);
    dim3 gg(NP / 128, MP / 128);   // 8 x 17 = 136 blocks
    k_mma<<<gg, 256, SMEM_TOT>>>(hptr);

    k_asad<<<(NN + 7) / 8, 256>>>(hptr, att_src, att_dst);
    k_edge1<<<(ET + 255) / 256, 256>>>(ei);
    k_edge2<<<(ET + 255) / 256, 256>>>(ei);
    k_scan<<<1, 256>>>();
    k_edge3<<<(ET + 255) / 256, 256>>>(ei);
    k_agg<<<MM, 256>>>(hptr, gat_b);

    // collapse MLP: v3 = W3@W4, v2 = W2@v3, v1 = W1@v2
    float* v3p; cudaGetSymbolAddress((void**)&v3p, d_v3);
    float* v2p; cudaGetSymbolAddress((void**)&v2p, d_v2);
    float* v1p; cudaGetSymbolAddress((void**)&v1p, d_v1);
    k_matvec<<<(512 + 7) / 8, 256>>>(W3, W4, v3p, 512, 64);
    k_matvec<<<(1024 + 7) / 8, 256>>>(W2, v3p, v2p, 1024, 512);
    k_matvec<<<(1802 + 7) / 8, 256>>>(W1, v2p, v1p, 1802, 1024);
    k_bc<<<1, 256>>>(b1, b2, b3, b4, W4);

    // MS_CAM stats + fusion + per-row dots
    k_rowstats<<<MM, 256>>>(mirna);
    k_fin1<<<1, 1>>>(lw1, lb1);
    k_stats2<<<MM, 256>>>(mirna, lw1, lb1);
    k_fin2<<<1, 1>>>(lw2);
    k_xg<<<1, 1024>>>(gw1, gb1, gw2, gb2);
    k_fused<<<MM, 256>>>(mirna, lw1, lb1);

    k_score<<<(NTRAIN + NTEST + 255) / 256, 256>>>(trainS, testS, out);
}

// round 9
// speedup vs baseline: 2.0922x; 1.1367x over previous
#include <cuda_runtime.h>
#include <cuda_fp16.h>
#include <cstdint>
#include <stdint.h>

#define NN 2060
#define FF 901
#define FFH 451          // half2 per padded row (902 cols)
#define MM 1778          // 901 + (2060-1183)
#define EE 131840        // NN*64
#define ET (EE + NN)     // edges + self loops
#define NTRAIN 100000
#define NTEST  30000
#define EPSF 1e-5f

// padded GEMM dims
#define MP 2176          // 17 * 128
#define KP2 2112         // 33 * 64
#define NP 1024          // 8 * 128
#define GBK 64
#define SKA 72           // A smem row stride (fp16 elems), 64 + 8 pad
#define SKB 136          // B smem row stride (fp16 elems), 128 + 8 pad
#define A_BYTES (128 * SKA * 2)            // 18432
#define B_BYTES (GBK * SKB * 2)            // 17408
#define STG (A_BYTES + B_BYTES)            // 35840
#define SMEM_TOT (2 * STG)                 // 71680

// ---------------- scratch (static device globals; no allocation) ----------------
__device__ float    d_h[NN * FF];
__device__ __half2  d_hh[NN * FFH];        // fp16 copy of h for the gather
__device__ float    d_g[NN * FF];
__device__ __half   d_Ah[MP * KP2];
__device__ __half   d_Bh[KP2 * NP];        // [K, N] row-major
__device__ float    d_as[NN], d_ad[NN];
__device__ float    d_e[ET];
__device__ unsigned d_emax[NN];
__device__ float    d_denom[NN];
__device__ int      d_deg[NN];
__device__ int      d_rowptr[NN + 1];
__device__ int      d_wp[NN];
__device__ int      d_ssrc[ET];
__device__ float    d_salpha[ET];
__device__ double   d_st1[5];
__device__ double   d_st2[2];
__device__ float    d_gp[MM * 2];
__device__ float    d_xgbn[MM * 2];
__device__ float    d_consts[8];
__device__ float    d_v3[512], d_v2[1024], d_v1[1802];
__device__ float    d_sA[MM], d_tB[MM];
__device__ float    d_bc;

__device__ __forceinline__ int drow(int m) { return m < 901 ? m : m + 282; }

__device__ __forceinline__ unsigned fenc(float f) {
    unsigned u = __float_as_uint(f);
    return (u & 0x80000000u) ? ~u : (u | 0x80000000u);
}
__device__ __forceinline__ float fdec(unsigned x) {
    return __uint_as_float((x & 0x80000000u) ? (x & 0x7FFFFFFFu) : ~x);
}

__device__ __forceinline__ float blockReduceSum(float v, float* sh) {
    int tid = threadIdx.x;
    sh[tid] = v; __syncthreads();
    for (int s = blockDim.x >> 1; s; s >>= 1) {
        if (tid < s) sh[tid] += sh[tid + s];
        __syncthreads();
    }
    float r = sh[0]; __syncthreads();
    return r;
}

// ---------------- init ----------------
__global__ void k_init() {
    int i = blockIdx.x * 256 + threadIdx.x;
    if (i < NN) { d_emax[i] = 0u; d_denom[i] = 0.f; d_deg[i] = 0; }
    if (i < 5) d_st1[i] = 0.0;
    if (i < 2) d_st2[i] = 0.0;
}

// ---------------- fp16 conversion ----------------
__device__ __forceinline__ unsigned pack2h(__half a, __half b) {
    return ((unsigned)__half_as_ushort(b) << 16) | (unsigned)__half_as_ushort(a);
}

__global__ __launch_bounds__(256) void k_convA(const float* __restrict__ x) {
    int i4 = (blockIdx.x * 256 + threadIdx.x) * 4;
    if (i4 >= MP * KP2) return;
    int m = i4 / KP2, k = i4 - m * KP2;
    float v[4];
    if (m < NN && k + 4 <= NN) {   // NN%4==0, KP2%4==0 -> no straddle
        float4 t = *(const float4*)(x + (size_t)m * NN + k);
        v[0] = t.x; v[1] = t.y; v[2] = t.z; v[3] = t.w;
    } else {
        v[0] = v[1] = v[2] = v[3] = 0.f;
    }
    __half h[4];
    #pragma unroll
    for (int j = 0; j < 4; j++) h[j] = __float2half(v[j]);
    *(uint2*)(d_Ah + i4) = make_uint2(pack2h(h[0], h[1]), pack2h(h[2], h[3]));
}

__global__ __launch_bounds__(256) void k_convB(const float* __restrict__ w) {
    int i4 = (blockIdx.x * 256 + threadIdx.x) * 4;
    if (i4 >= KP2 * NP) return;
    int k = i4 / NP, n = i4 - k * NP;
    __half h[4];
    #pragma unroll
    for (int j = 0; j < 4; j++) {
        int nn = n + j;
        float v = (k < NN && nn < FF) ? w[(size_t)k * FF + nn] : 0.f;
        h[j] = __float2half(v);
    }
    *(uint2*)(d_Bh + i4) = make_uint2(pack2h(h[0], h[1]), pack2h(h[2], h[3]));
}

// ---------------- tensor-core fp16 GEMM ----------------
__device__ __forceinline__ void ldsm4(unsigned& r0, unsigned& r1, unsigned& r2, unsigned& r3, unsigned a) {
    asm volatile("ldmatrix.sync.aligned.m8n8.x4.shared.b16 {%0,%1,%2,%3}, [%4];"
                 : "=r"(r0), "=r"(r1), "=r"(r2), "=r"(r3) : "r"(a));
}
__device__ __forceinline__ void ldsm4t(unsigned& r0, unsigned& r1, unsigned& r2, unsigned& r3, unsigned a) {
    asm volatile("ldmatrix.sync.aligned.m8n8.x4.trans.shared.b16 {%0,%1,%2,%3}, [%4];"
                 : "=r"(r0), "=r"(r1), "=r"(r2), "=r"(r3) : "r"(a));
}
__device__ __forceinline__ void mma16816(float* c, const unsigned* a, unsigned b0, unsigned b1) {
    asm volatile("mma.sync.aligned.m16n8k16.row.col.f32.f16.f16.f32 "
                 "{%0,%1,%2,%3},{%4,%5,%6,%7},{%8,%9},{%0,%1,%2,%3};"
                 : "+f"(c[0]), "+f"(c[1]), "+f"(c[2]), "+f"(c[3])
                 : "r"(a[0]), "r"(a[1]), "r"(a[2]), "r"(a[3]), "r"(b0), "r"(b1));
}
__device__ __forceinline__ void cp16(unsigned s, const void* g) {
    asm volatile("cp.async.cg.shared.global [%0], [%1], 16;" :: "r"(s), "l"(g));
}

__device__ __forceinline__ void load_stage(unsigned sbase, int stage, int k0,
                                           int tid, int m0, int n0) {
    unsigned st = sbase + stage * STG;
    #pragma unroll
    for (int i = 0; i < 4; i++) {
        int id = tid + i * 256;
        // A: 128 rows x 64 fp16, 8 x 16B chunks per row -> 1024 chunks
        int ar = id >> 3, ac = (id & 7) * 8;
        cp16(st + (unsigned)(ar * SKA + ac) * 2, d_Ah + (size_t)(m0 + ar) * KP2 + k0 + ac);
        // B: 64 rows x 128 fp16, 16 x 16B chunks per row -> 1024 chunks
        int br = id >> 4, bcg = (id & 15) * 8;
        cp16(st + A_BYTES + (unsigned)(br * SKB + bcg) * 2,
             d_Bh + (size_t)(k0 + br) * NP + n0 + bcg);
    }
}

__global__ __launch_bounds__(256) void k_mma(float* __restrict__ C) {
    extern __shared__ __align__(16) __half smem[];
    unsigned sbase = (unsigned)__cvta_generic_to_shared(smem);
    int tid = threadIdx.x;
    int warp = tid >> 5, lane = tid & 31;
    int wm = (warp & 3) * 32;
    int wn = (warp >> 2) * 64;
    int m0 = blockIdx.y * 128;
    int n0 = blockIdx.x * 128;

    float acc[2][8][4];
    #pragma unroll
    for (int i = 0; i < 2; i++)
        #pragma unroll
        for (int j = 0; j < 8; j++)
            #pragma unroll
            for (int q = 0; q < 4; q++) acc[i][j][q] = 0.f;

    const int NT = KP2 / GBK;  // 33

    load_stage(sbase, 0, 0, tid, m0, n0);
    asm volatile("cp.async.commit_group;");

    for (int t = 0; t < NT; t++) {
        if (t + 1 < NT) {
            load_stage(sbase, (t + 1) & 1, (t + 1) * GBK, tid, m0, n0);
            asm volatile("cp.async.commit_group;");
            asm volatile("cp.async.wait_group 1;");
        } else {
            asm volatile("cp.async.wait_group 0;");
        }
        __syncthreads();

        unsigned abase = sbase + (t & 1) * STG;
        unsigned bbase = abase + A_BYTES;

        #pragma unroll
        for (int ks = 0; ks < 4; ks++) {
            unsigned ah[2][4], bh[4][4];
            #pragma unroll
            for (int mi = 0; mi < 2; mi++) {
                int row = wm + mi * 16 + (lane & 15);
                int col = ks * 16 + (lane >> 4) * 8;
                unsigned off = (unsigned)(row * SKA + col) * 2;
                ldsm4(ah[mi][0], ah[mi][1], ah[mi][2], ah[mi][3], abase + off);
            }
            #pragma unroll
            for (int nj = 0; nj < 4; nj++) {
                int row = ks * 16 + (lane & 15);
                int col = wn + nj * 16 + (lane >> 4) * 8;
                unsigned off = (unsigned)(row * SKB + col) * 2;
                ldsm4t(bh[nj][0], bh[nj][1], bh[nj][2], bh[nj][3], bbase + off);
            }
            #pragma unroll
            for (int mi = 0; mi < 2; mi++) {
                #pragma unroll
                for (int nj = 0; nj < 4; nj++) {
                    #pragma unroll
                    for (int hf = 0; hf < 2; hf++) {
                        mma16816(acc[mi][nj * 2 + hf], ah[mi],
                                 bh[nj][hf * 2], bh[nj][hf * 2 + 1]);
                    }
                }
            }
        }
        __syncthreads();
    }

    // epilogue: fp32 h + packed fp16 copy for the gather
    #pragma unroll
    for (int mi = 0; mi < 2; mi++) {
        #pragma unroll
        for (int t8 = 0; t8 < 8; t8++) {
            int m = m0 + wm + mi * 16 + (lane >> 2);
            int n = n0 + wn + t8 * 8 + (lane & 3) * 2;   // always even
            float* c = acc[mi][t8];
            if (n < FF) {
                bool p1 = (n + 1 < FF);
                if (m < NN) {
                    C[(size_t)m * FF + n] = c[0];
                    if (p1) C[(size_t)m * FF + n + 1] = c[1];
                    d_hh[(size_t)m * FFH + (n >> 1)] = __floats2half2_rn(c[0], p1 ? c[1] : 0.f);
                }
                if (m + 8 < NN) {
                    C[(size_t)(m + 8) * FF + n] = c[2];
                    if (p1) C[(size_t)(m + 8) * FF + n + 1] = c[3];
                    d_hh[(size_t)(m + 8) * FFH + (n >> 1)] = __floats2half2_rn(c[2], p1 ? c[3] : 0.f);
                }
            }
        }
    }
}

// ---------------- attention logits precompute ----------------
__global__ void k_asad(const float* __restrict__ h, const float* __restrict__ att_s,
                       const float* __restrict__ att_d) {
    int w = (blockIdx.x * blockDim.x + threadIdx.x) >> 5;
    int lane = threadIdx.x & 31;
    if (w >= NN) return;
    const float* hr = h + (size_t)w * FF;
    float s = 0.f, d = 0.f;
    for (int f = lane; f < FF; f += 32) { float hv = hr[f]; s += hv * att_s[f]; d += hv * att_d[f]; }
    for (int o = 16; o; o >>= 1) { s += __shfl_down_sync(~0u, s, o); d += __shfl_down_sync(~0u, d, o); }
    if (!lane) { d_as[w] = s; d_ad[w] = d; }
}

__global__ void k_edge1(const int* __restrict__ ei) {
    int j = blockIdx.x * 256 + threadIdx.x;
    if (j >= ET) return;
    int src, dst;
    if (j < EE) { src = ei[j]; dst = ei[EE + j]; } else { src = dst = j - EE; }
    float e = d_as[src] + d_ad[dst];
    e = e >= 0.f ? e : 0.2f * e;
    d_e[j] = e;
    atomicMax(&d_emax[dst], fenc(e));
    atomicAdd(&d_deg[dst], 1);
}

__global__ void k_edge2(const int* __restrict__ ei) {
    int j = blockIdx.x * 256 + threadIdx.x;
    if (j >= ET) return;
    int dst = (j < EE) ? ei[EE + j] : (j - EE);
    float ex = expf(d_e[j] - fdec(d_emax[dst]));
    d_e[j] = ex;
    atomicAdd(&d_denom[dst], ex);
}

__global__ void k_scan() {
    __shared__ int partial[256];
    int tid = threadIdx.x;
    const int CH = (NN + 255) / 256;   // 9
    int base = tid * CH;
    int loc[9];
    int sum = 0;
    for (int i = 0; i < CH; i++) {
        int idx = base + i;
        int v = (idx < NN) ? d_deg[idx] : 0;
        loc[i] = sum; sum += v;
    }
    partial[tid] = sum; __syncthreads();
    if (tid == 0) {
        int run = 0;
        for (int i = 0; i < 256; i++) { int v = partial[i]; partial[i] = run; run += v; }
        d_rowptr[NN] = run;
    }
    __syncthreads();
    int off = partial[tid];
    for (int i = 0; i < CH; i++) {
        int idx = base + i;
        if (idx < NN) { d_rowptr[idx] = off + loc[i]; d_wp[idx] = off + loc[i]; }
    }
}

__global__ void k_edge3(const int* __restrict__ ei) {
    int j = blockIdx.x * 256 + threadIdx.x;
    if (j >= ET) return;
    int src, dst;
    if (j < EE) { src = ei[j]; dst = ei[EE + j]; } else { src = dst = j - EE; }
    float alpha = d_e[j] / d_denom[dst];
    int pos = atomicAdd(&d_wp[dst], 1);
    d_ssrc[pos] = src;
    d_salpha[pos] = alpha;
}

// aggregate (fp16 gather) only the 1778 rows consumed downstream
__global__ __launch_bounds__(256) void k_agg(const float* __restrict__ gat_b) {
    int d = drow(blockIdx.x);
    int start = d_rowptr[d], end = d_rowptr[d + 1];
    __shared__ int ss[128];
    __shared__ float sa[128];
    float2 acc[2];
    acc[0] = make_float2(0.f, 0.f);
    acc[1] = make_float2(0.f, 0.f);
    for (int e0 = start; e0 < end; e0 += 128) {
        int cnt = min(128, end - e0);
        if (threadIdx.x < cnt) { ss[threadIdx.x] = d_ssrc[e0 + threadIdx.x]; sa[threadIdx.x] = d_salpha[e0 + threadIdx.x]; }
        __syncthreads();
        for (int i = 0; i < cnt; i++) {
            const __half2* hr = d_hh + (size_t)ss[i] * FFH;
            float al = sa[i];
            #pragma unroll
            for (int q = 0; q < 2; q++) {
                int f = threadIdx.x + q * 256;
                if (f < FFH) {
                    float2 v = __half22float2(hr[f]);
                    acc[q].x = fmaf(al, v.x, acc[q].x);
                    acc[q].y = fmaf(al, v.y, acc[q].y);
                }
            }
        }
        __syncthreads();
    }
    #pragma unroll
    for (int q = 0; q < 2; q++) {
        int f = threadIdx.x + q * 256;
        if (f < FFH) {
            int col = f * 2;
            float v0 = acc[q].x + gat_b[col];
            d_g[(size_t)d * FF + col] = v0 > 0.f ? v0 : 0.f;
            if (col + 1 < FF) {
                float v1 = acc[q].y + gat_b[col + 1];
                d_g[(size_t)d * FF + col + 1] = v1 > 0.f ? v1 : 0.f;
            }
        }
    }
}

// ---------------- MLP collapse: v1 = W1 @ W2 @ W3 @ W4 ----------------
__global__ void k_matvec(const float* __restrict__ Wm, const float* __restrict__ v,
                         float* __restrict__ o, int rows, int cols) {
    int r = (blockIdx.x * blockDim.x + threadIdx.x) >> 5;
    int lane = threadIdx.x & 31;
    if (r >= rows) return;
    const float* Wr = Wm + (size_t)r * cols;
    float acc = 0.f;
    for (int c = lane; c < cols; c += 32) acc = fmaf(Wr[c], v[c], acc);
    for (int o2 = 16; o2; o2 >>= 1) acc += __shfl_down_sync(~0u, acc, o2);
    if (!lane) o[r] = acc;
}

__global__ void k_bc(const float* __restrict__ b1, const float* __restrict__ b2,
                     const float* __restrict__ b3, const float* __restrict__ b4,
                     const float* __restrict__ W4) {
    __shared__ float sh[256];
    float acc = 0.f;
    for (int i = threadIdx.x; i < 1024; i += 256) acc += b1[i] * d_v2[i];
    for (int i = threadIdx.x; i < 512; i += 256) acc += b2[i] * d_v3[i];
    for (int i = threadIdx.x; i < 64; i += 256) acc += b3[i] * W4[i];
    acc = blockReduceSum(acc, sh);
    if (threadIdx.x == 0) d_bc = acc + b4[0];
}

// ---------------- MS_CAM statistics ----------------
__global__ __launch_bounds__(256) void k_rowstats(const float* __restrict__ mirna) {
    __shared__ float sh[256];
    int m = blockIdx.x;
    const float* dvr = d_g + (size_t)drow(m) * FF;
    const float* mir = mirna + (size_t)m * FF;
    float sdv = 0, smi = 0, sdv2 = 0, smi2 = 0, sx = 0;
    for (int f = threadIdx.x; f < FF; f += 256) {
        float dv = dvr[f], mi = mir[f];
        sdv += dv; smi += mi; sdv2 += dv * dv; smi2 += mi * mi; sx += dv * mi;
    }
    sdv = blockReduceSum(sdv, sh);
    smi = blockReduceSum(smi, sh);
    sdv2 = blockReduceSum(sdv2, sh);
    smi2 = blockReduceSum(smi2, sh);
    sx = blockReduceSum(sx, sh);
    if (threadIdx.x == 0) {
        d_gp[2 * m] = sdv / (float)FF;
        d_gp[2 * m + 1] = smi / (float)FF;
        atomicAdd(&d_st1[0], (double)sdv);
        atomicAdd(&d_st1[1], (double)smi);
        atomicAdd(&d_st1[2], (double)sdv2);
        atomicAdd(&d_st1[3], (double)smi2);
        atomicAdd(&d_st1[4], (double)sx);
    }
}

__global__ void k_fin1(const float* __restrict__ lw1, const float* __restrict__ lb1) {
    double cnt = (double)MM * FF;
    double a = lw1[0], b = lw1[1], c0 = lb1[0];
    double mean = (a * d_st1[0] + b * d_st1[1]) / cnt + c0;
    double ex2 = (a * a * d_st1[2] + b * b * d_st1[3] + 2.0 * a * b * d_st1[4]
                  + 2.0 * a * c0 * d_st1[0] + 2.0 * b * c0 * d_st1[1]) / cnt + c0 * c0;
    double var = ex2 - mean * mean;
    d_consts[0] = (float)mean;
    d_consts[1] = rsqrtf((float)var + EPSF);
}

__global__ __launch_bounds__(256) void k_stats2(const float* __restrict__ mirna,
                                                const float* __restrict__ lw1,
                                                const float* __restrict__ lb1) {
    __shared__ float sh[256];
    int m = blockIdx.x;
    const float* dvr = d_g + (size_t)drow(m) * FF;
    const float* mir = mirna + (size_t)m * FF;
    float a = lw1[0], b = lw1[1], c0 = lb1[0];
    float mu1 = d_consts[0], rs1 = d_consts[1];
    float su = 0, su2 = 0;
    for (int f = threadIdx.x; f < FF; f += 256) {
        float xlp = fmaf(a, dvr[f], fmaf(b, mir[f], c0));
        float u = (xlp - mu1) * rs1;
        u = u > 0.f ? u : 0.f;
        su += u; su2 += u * u;
    }
    su = blockReduceSum(su, sh);
    su2 = blockReduceSum(su2, sh);
    if (threadIdx.x == 0) {
        atomicAdd(&d_st2[0], (double)su);
        atomicAdd(&d_st2[1], (double)su2);
    }
}

__global__ void k_fin2(const float* __restrict__ lw2) {
    double cnt = (double)MM * FF;
    double muu = d_st2[0] / cnt;
    double varu = d_st2[1] / cnt - muu * muu;
    d_consts[2] = (float)muu;
    float w0 = lw2[0], w1 = lw2[1];
    d_consts[3] = w0 * rsqrtf((float)(w0 * w0 * varu) + EPSF);
    d_consts[4] = w1 * rsqrtf((float)(w1 * w1 * varu) + EPSF);
}

__global__ __launch_bounds__(1024) void k_xg(const float* __restrict__ gw1, const float* __restrict__ gb1,
                                             const float* __restrict__ gw2, const float* __restrict__ gb2) {
    __shared__ float red[1024];
    int tid = threadIdx.x;
    float g10 = gw1[0], g11 = gw1[1], gb = gb1[0];
    bool h0 = tid < MM, h1 = tid + 1024 < MM;
    float x0 = 0.f, x1 = 0.f;
    if (h0) x0 = fmaf(d_gp[2 * tid], g10, fmaf(d_gp[2 * tid + 1], g11, gb));
    if (h1) x1 = fmaf(d_gp[2 * (tid + 1024)], g10, fmaf(d_gp[2 * (tid + 1024) + 1], g11, gb));

    red[tid] = (h0 ? x0 : 0.f) + (h1 ? x1 : 0.f); __syncthreads();
    for (int s = 512; s; s >>= 1) { if (tid < s) red[tid] += red[tid + s]; __syncthreads(); }
    float mean = red[0] / (float)MM; __syncthreads();

    float dx0 = x0 - mean, dx1 = x1 - mean;
    red[tid] = (h0 ? dx0 * dx0 : 0.f) + (h1 ? dx1 * dx1 : 0.f); __syncthreads();
    for (int s = 512; s; s >>= 1) { if (tid < s) red[tid] += red[tid + s]; __syncthreads(); }
    float rs = rsqrtf(red[0] / (float)MM + EPSF); __syncthreads();

    float u0 = h0 ? fmaxf(dx0 * rs, 0.f) : 0.f;
    float u1 = h1 ? fmaxf(dx1 * rs, 0.f) : 0.f;

    red[tid] = u0 + u1; __syncthreads();
    for (int s = 512; s; s >>= 1) { if (tid < s) red[tid] += red[tid + s]; __syncthreads(); }
    float mu = red[0] / (float)MM; __syncthreads();

    float du0 = u0 - mu, du1 = u1 - mu;
    red[tid] = (h0 ? du0 * du0 : 0.f) + (h1 ? du1 * du1 : 0.f); __syncthreads();
    for (int s = 512; s; s >>= 1) { if (tid < s) red[tid] += red[tid + s]; __syncthreads(); }
    float varg = red[0] / (float)MM;

    float w0 = gw2[0], w1 = gw2[1];
    float sc0 = w0 * rsqrtf(w0 * w0 * varg + EPSF);
    float sc1 = w1 * rsqrtf(w1 * w1 * varg + EPSF);
    if (h0) { d_xgbn[2 * tid] = du0 * sc0; d_xgbn[2 * tid + 1] = du0 * sc1; }
    if (h1) { d_xgbn[2 * (tid + 1024)] = du1 * sc0; d_xgbn[2 * (tid + 1024) + 1] = du1 * sc1; }
}

__global__ __launch_bounds__(256) void k_fused(const float* __restrict__ mirna,
                                               const float* __restrict__ lw1,
                                               const float* __restrict__ lb1) {
    __shared__ float sh[256];
    int m = blockIdx.x;
    const float* dvr = d_g + (size_t)drow(m) * FF;
    const float* mir = mirna + (size_t)m * FF;
    float a = lw1[0], b = lw1[1], c0 = lb1[0];
    float mu1 = d_consts[0], rs1 = d_consts[1];
    float muu = d_consts[2], sc0 = d_consts[3], sc1 = d_consts[4];
    float xg0 = d_xgbn[2 * m], xg1 = d_xgbn[2 * m + 1];
    float accS = 0.f, accT = 0.f;
    for (int f = threadIdx.x; f < FF; f += 256) {
        float dv = dvr[f], mi = mir[f];
        float xlp = fmaf(a, dv, fmaf(b, mi, c0));
        float u = (xlp - mu1) * rs1;
        u = u > 0.f ? u : 0.f;
        float um = u - muu;
        float z0 = fmaf(um, sc0, xg0);
        float z1 = fmaf(um, sc1, xg1);
        float w0 = 1.f / (1.f + expf(-z0));
        float w1 = 1.f / (1.f + expf(-z1));
        float fu = 0.5f * (dv * w0 + mi * w1);
        accS = fmaf(fu, d_v1[f], accS);
        accT = fmaf(fu, d_v1[901 + f], accT);
    }
    accS = blockReduceSum(accS, sh);
    accT = blockReduceSum(accT, sh);
    if (threadIdx.x == 0) { d_sA[m] = accS; d_tB[m] = accT; }
}

__global__ void k_score(const int* __restrict__ tr, const int* __restrict__ te,
                        float* __restrict__ out) {
    int i = blockIdx.x * 256 + threadIdx.x;
    if (i >= NTRAIN + NTEST) return;
    int p0, p1;
    if (i < NTRAIN) { p0 = tr[2 * i]; p1 = tr[2 * i + 1]; }
    else { int j = i - NTRAIN; p0 = te[2 * j]; p1 = te[2 * j + 1]; }
    float z = d_sA[p0] + d_tB[p1] + d_bc;
    out[i] = 1.f / (1.f + expf(-z));
}

// ---------------- launch ----------------
extern "C" void kernel_launch(void* const* d_in, const int* in_sizes, int n_in,
                              void* d_out, int out_size) {
    const float* x_feat  = (const float*)d_in[0];
    const float* mirna   = (const float*)d_in[1];
    const float* Wg      = (const float*)d_in[2];
    const float* att_src = (const float*)d_in[3];
    const float* att_dst = (const float*)d_in[4];
    const float* gat_b   = (const float*)d_in[5];
    const float* lw1     = (const float*)d_in[6];
    const float* lb1     = (const float*)d_in[7];
    const float* lw2     = (const float*)d_in[8];
    const float* gw1     = (const float*)d_in[10];
    const float* gb1     = (const float*)d_in[11];
    const float* gw2     = (const float*)d_in[12];
    const float* gb2     = (const float*)d_in[13];
    const float* W1      = (const float*)d_in[14];
    const float* b1      = (const float*)d_in[15];
    const float* W2      = (const float*)d_in[16];
    const float* b2      = (const float*)d_in[17];
    const float* W3      = (const float*)d_in[18];
    const float* b3      = (const float*)d_in[19];
    const float* W4      = (const float*)d_in[20];
    const float* b4      = (const float*)d_in[21];
    const int*   ei      = (const int*)d_in[22];
    const int*   trainS  = (const int*)d_in[23];
    const int*   testS   = (const int*)d_in[24];
    float* out = (float*)d_out;

    float* hptr;  cudaGetSymbolAddress((void**)&hptr, d_h);

    cudaFuncSetAttribute(k_mma, cudaFuncAttributeMaxDynamicSharedMemorySize, SMEM_TOT);

    k_init<<<(NN + 255) / 256, 256>>>();

    // h = x_feat @ Wg via fp16 tensor cores (single product)
    k_convA<<<(MP * KP2 / 4 + 255) / 256, 256>>>(x_feat);
    k_convB<<<(KP2 * NP / 4 + 255) / 256, 256>>>(Wg);
    dim3 gg(NP / 128, MP / 128);   // 8 x 17 = 136 blocks
    k_mma<<<gg, 256, SMEM_TOT>>>(hptr);

    k_asad<<<(NN + 7) / 8, 256>>>(hptr, att_src, att_dst);
    k_edge1<<<(ET + 255) / 256, 256>>>(ei);
    k_edge2<<<(ET + 255) / 256, 256>>>(ei);
    k_scan<<<1, 256>>>();
    k_edge3<<<(ET + 255) / 256, 256>>>(ei);
    k_agg<<<MM, 256>>>(gat_b);

    // collapse MLP: v3 = W3@W4, v2 = W2@v3, v1 = W1@v2
    float* v3p; cudaGetSymbolAddress((void**)&v3p, d_v3);
    float* v2p; cudaGetSymbolAddress((void**)&v2p, d_v2);
    float* v1p; cudaGetSymbolAddress((void**)&v1p, d_v1);
    k_matvec<<<(512 + 7) / 8, 256>>>(W3, W4, v3p, 512, 64);
    k_matvec<<<(1024 + 7) / 8, 256>>>(W2, v3p, v2p, 1024, 512);
    k_matvec<<<(1802 + 7) / 8, 256>>>(W1, v2p, v1p, 1802, 1024);
    k_bc<<<1, 256>>>(b1, b2, b3, b4, W4);

    // MS_CAM stats + fusion + per-row dots
    k_rowstats<<<MM, 256>>>(mirna);
    k_fin1<<<1, 1>>>(lw1, lb1);
    k_stats2<<<MM, 256>>>(mirna, lw1, lb1);
    k_fin2<<<1, 1>>>(lw2);
    k_xg<<<1, 1024>>>(gw1, gb1, gw2, gb2);
    k_fused<<<MM, 256>>>(mirna, lw1, lb1);

    k_score<<<(NTRAIN + NTEST + 255) / 256, 256>>>(trainS, testS, out);
}